// round 1
// baseline (speedup 1.0000x reference)
#include <cuda_runtime.h>
#include <math.h>

// Problem constants (fixed by setup_inputs)
#define D_DIM   1024
#define T_TREES 16
#define N_INT   15
#define N_LEAF  16
#define NCOLS   256     // 240 decision logits + 16 gate logits
#define O_DIM   512
#define M_MAX   8192    // B*S = 4*2048

// ---------------- scratch (device globals; no allocation allowed) ----------
__device__ float g_W[NCOLS * D_DIM];          // packed weights, row = output col, K-major
__device__ float g_bias[NCOLS];               // decision biases (0..239) + gate bias (240..255)
__device__ float g_invtemp[T_TREES * N_INT];  // 1 / softplus(ntl + 0.5413)
__device__ float g_logits[M_MAX * NCOLS];     // GEMM1 output
__device__ float g_wleaf[M_MAX * NCOLS];      // gate_t * leafprob_{t,l}

// ---------------- kernel 0: pack weights / bias / temps --------------------
__global__ void pack_weights(const float* __restrict__ dw,
                             const float* __restrict__ db,
                             const float* __restrict__ gw,
                             const float* __restrict__ gb,
                             const float* __restrict__ ntl) {
    int tid = blockIdx.x * blockDim.x + threadIdx.x;
    int stride = gridDim.x * blockDim.x;
    // decision weights: [T, N_INT, D] is already [240, 1024] row-major
    for (int i = tid; i < 240 * D_DIM; i += stride) g_W[i] = dw[i];
    // gate rows: W[240+t][d] = gate_w[d][t]
    for (int i = tid; i < 16 * D_DIM; i += stride) {
        int t = i / D_DIM, d = i % D_DIM;
        g_W[(240 + t) * D_DIM + d] = gw[d * 16 + t];
    }
    if (tid < 240) {
        g_bias[tid] = db[tid];
        float z = ntl[tid] + 0.5413f;
        float sp = (z > 20.f) ? z : log1pf(expf(z));   // softplus, TEMP = 1
        g_invtemp[tid] = 1.0f / sp;
    } else if (tid < 256) {
        g_bias[tid] = gb[tid - 240];
    }
}

// ---------------- tiled fp32 GEMM: C[M,N] = A[M,K] @ B (+bias) -------------
// B_KMAJOR = true : B is [N, K] row-major (dot along contiguous K)
// B_KMAJOR = false: B is [K, N] row-major
// Tile: BM=64, BN=128, BK=32, 256 threads, per-thread 8x4 microtile.
template <bool B_KMAJOR>
__global__ __launch_bounds__(256)
void gemm_kernel(const float* __restrict__ A,
                 const float* __restrict__ B,
                 const float* __restrict__ bias,
                 float* __restrict__ C,
                 int M, int N, int K) {
    const int BM = 64, BN = 128, BK = 32;
    __shared__ float As[BK][BM + 1];   // padded: conflict-free stores, broadcast reads
    __shared__ float Bs[BK][BN + 1];

    int tid = threadIdx.x;
    int tm = tid >> 5;    // 0..7
    int tn = tid & 31;    // 0..31
    int m0 = blockIdx.x * BM;
    int n0 = blockIdx.y * BN;

    float acc[8][4];
#pragma unroll
    for (int i = 0; i < 8; i++)
#pragma unroll
        for (int j = 0; j < 4; j++) acc[i][j] = 0.f;

    for (int k0 = 0; k0 < K; k0 += BK) {
        // A tile: 64x32, coalesced along K, transposed into smem
#pragma unroll
        for (int i = 0; i < 8; i++) {
            int idx = tid + i * 256;
            int m = idx >> 5;
            int k = idx & 31;
            As[k][m] = A[(size_t)(m0 + m) * K + k0 + k];
        }
        // B tile: 128x32
        if (B_KMAJOR) {
#pragma unroll
            for (int i = 0; i < 16; i++) {
                int idx = tid + i * 256;
                int n = idx >> 5;
                int k = idx & 31;
                Bs[k][n] = B[(size_t)(n0 + n) * K + k0 + k];
            }
        } else {
#pragma unroll
            for (int i = 0; i < 16; i++) {
                int idx = tid + i * 256;
                int k = idx >> 7;
                int n = idx & 127;
                Bs[k][n] = B[(size_t)(k0 + k) * N + n0 + n];
            }
        }
        __syncthreads();

#pragma unroll
        for (int k = 0; k < BK; k++) {
            float a[8], b[4];
#pragma unroll
            for (int i = 0; i < 8; i++) a[i] = As[k][tm * 8 + i];   // broadcast
#pragma unroll
            for (int j = 0; j < 4; j++) b[j] = Bs[k][tn + 32 * j];  // lane-consecutive
#pragma unroll
            for (int i = 0; i < 8; i++)
#pragma unroll
                for (int j = 0; j < 4; j++)
                    acc[i][j] = fmaf(a[i], b[j], acc[i][j]);
        }
        __syncthreads();
    }

#pragma unroll
    for (int j = 0; j < 4; j++) {
        int n = n0 + tn + 32 * j;
        float bv = bias ? bias[n] : 0.f;
#pragma unroll
        for (int i = 0; i < 8; i++) {
            int m = m0 + tm * 8 + i;
            C[(size_t)m * N + n] = acc[i][j] + bv;
        }
    }
}

// ---------------- kernel 2: gate softmax + sigmoids + path products --------
// One warp per token. Lane t < 16 owns tree t.
__global__ __launch_bounds__(256)
void build_w_kernel(int M) {
    int warp = (blockIdx.x * blockDim.x + threadIdx.x) >> 5;
    int lane = threadIdx.x & 31;
    if (warp >= M) return;

    const float* lrow = &g_logits[(size_t)warp * NCOLS];
    float* wrow = &g_wleaf[(size_t)warp * NCOLS];

    // gate softmax over 16 (lanes 16..31 carry -inf / 0)
    float gl = (lane < 16) ? lrow[240 + lane] : -INFINITY;
    float mx = gl;
#pragma unroll
    for (int o = 16; o > 0; o >>= 1) mx = fmaxf(mx, __shfl_xor_sync(0xffffffffu, mx, o));
    float e = (lane < 16) ? expf(gl - mx) : 0.f;
    float s = e;
#pragma unroll
    for (int o = 16; o > 0; o >>= 1) s += __shfl_xor_sync(0xffffffffu, s, o);
    float gate = e / s;

    if (lane < 16) {
        int t = lane;
        float dec[N_INT];
#pragma unroll
        for (int n = 0; n < N_INT; n++) {
            float z = lrow[t * N_INT + n] * g_invtemp[t * N_INT + n];
            dec[n] = 1.f / (1.f + expf(-z));
        }
#pragma unroll
        for (int leaf = 0; leaf < N_LEAF; leaf++) {
            float p = gate;
            int node = 0;
#pragma unroll
            for (int d = 0; d < 4; d++) {
                int bit = (leaf >> (3 - d)) & 1;
                float dv = dec[node];           // node is compile-time after unroll
                p *= bit ? (1.f - dv) : dv;
                node = 2 * node + 1 + bit;
            }
            wrow[t * N_LEAF + leaf] = p;
        }
    }
}

// ---------------- kernel 4: in-place LayerNorm over O=512 ------------------
__global__ __launch_bounds__(256)
void layernorm_kernel(float* __restrict__ out,
                      const float* __restrict__ gamma,
                      const float* __restrict__ beta,
                      int M) {
    int warp = (blockIdx.x * blockDim.x + threadIdx.x) >> 5;
    int lane = threadIdx.x & 31;
    if (warp >= M) return;
    float* row = out + (size_t)warp * O_DIM;

    float v[16];
    float s = 0.f, sq = 0.f;
#pragma unroll
    for (int i = 0; i < 16; i++) {
        v[i] = row[lane + 32 * i];
        s += v[i];
        sq += v[i] * v[i];
    }
#pragma unroll
    for (int o = 16; o > 0; o >>= 1) {
        s  += __shfl_xor_sync(0xffffffffu, s, o);
        sq += __shfl_xor_sync(0xffffffffu, sq, o);
    }
    float mu = s * (1.f / O_DIM);
    float var = sq * (1.f / O_DIM) - mu * mu;
    float inv = rsqrtf(var + 1e-5f);
#pragma unroll
    for (int i = 0; i < 16; i++) {
        int c = lane + 32 * i;
        row[c] = (v[i] - mu) * inv * gamma[c] + beta[c];
    }
}

// ---------------- launch ----------------------------------------------------
extern "C" void kernel_launch(void* const* d_in, const int* in_sizes, int n_in,
                              void* d_out, int out_size) {
    const float* x     = (const float*)d_in[0];   // (B,S,D)
    const float* dw    = (const float*)d_in[1];   // (T,15,D)
    const float* db    = (const float*)d_in[2];   // (T,15)
    const float* leaf  = (const float*)d_in[3];   // (T,16,O)  == [256,512]
    const float* gw    = (const float*)d_in[4];   // (D,T)
    const float* gb    = (const float*)d_in[5];   // (T,)
    const float* ntl   = (const float*)d_in[6];   // (T,15)
    const float* gamma = (const float*)d_in[7];   // (O,)
    const float* beta  = (const float*)d_in[8];   // (O,)
    float* out = (float*)d_out;

    int M = in_sizes[0] / D_DIM;   // B*S = 8192

    void *pW = nullptr, *pBias = nullptr, *pLogits = nullptr, *pWleaf = nullptr;
    cudaGetSymbolAddress(&pW, g_W);
    cudaGetSymbolAddress(&pBias, g_bias);
    cudaGetSymbolAddress(&pLogits, g_logits);
    cudaGetSymbolAddress(&pWleaf, g_wleaf);

    // 0) pack weights (graph-captured each replay; deterministic)
    pack_weights<<<128, 256>>>(dw, db, gw, gb, ntl);

    // 1) GEMM1: logits[M,256] = x @ W^T + bias    (W is [256,1024] K-major)
    dim3 g1(M / 64, NCOLS / 128);
    gemm_kernel<true><<<g1, 256>>>(x, (const float*)pW, (const float*)pBias,
                                   (float*)pLogits, M, NCOLS, D_DIM);

    // 2) gate softmax + sigmoids + path products -> Wl[M,256]
    build_w_kernel<<<(M + 7) / 8, 256>>>(M);

    // 3) GEMM2: out[M,512] = Wl @ leaf_outputs    (leaf is [256,512] row-major)
    dim3 g2(M / 64, O_DIM / 128);
    gemm_kernel<false><<<g2, 256>>>((const float*)pWleaf, leaf, nullptr,
                                    out, M, O_DIM, NCOLS);

    // 4) in-place LayerNorm over the last dim
    layernorm_kernel<<<(M + 7) / 8, 256>>>(out, gamma, beta, M);
}

// round 3
// speedup vs baseline: 1.6029x; 1.6029x over previous
#include <cuda_runtime.h>
#include <cuda_bf16.h>
#include <math.h>
#include <stdint.h>

// ---------------- problem constants ----------------
#define D_DIM 1024
#define NCOLS 256      // 240 decision + 16 gate logits
#define O_DIM 512
#define M_MAX 8192

// split-bf16 buffers:
// GEMM1: A1 [M, 2048] = [hi|lo],  B1 [256, 3072] = [hi|hi|lo]
// GEMM2: A2 [M, 512]  = [hi|lo],  B2 [512, 768]  = [hi|hi|lo]
__device__ __align__(16) __nv_bfloat16 g_A1[M_MAX * 2048];
__device__ __align__(16) __nv_bfloat16 g_B1[NCOLS * 3072];
__device__ __align__(16) __nv_bfloat16 g_A2[M_MAX * 512];
__device__ __align__(16) __nv_bfloat16 g_B2[O_DIM * 768];
__device__ float g_logits[M_MAX * NCOLS];
__device__ float g_bias[NCOLS];
__device__ float g_invtemp[240];

// ---------------- helpers ----------------
__device__ __forceinline__ uint32_t smem_u32(const void* p) {
    uint32_t a;
    asm("{ .reg .u64 t; cvta.to.shared.u64 t, %1; cvt.u32.u64 %0, t; }"
        : "=r"(a) : "l"(p));
    return a;
}
__device__ __forceinline__ void cp16(uint32_t s, const void* g) {
    asm volatile("cp.async.cg.shared.global [%0], [%1], 16;" :: "r"(s), "l"(g));
}
#define CP_COMMIT() asm volatile("cp.async.commit_group;" ::: "memory")
#define CP_WAIT(n)  asm volatile("cp.async.wait_group %0;" :: "n"(n) : "memory")

__device__ __forceinline__ void ldsm4(uint32_t r[4], uint32_t addr) {
    asm volatile("ldmatrix.sync.aligned.m8n8.x4.shared.b16 {%0,%1,%2,%3}, [%4];"
                 : "=r"(r[0]), "=r"(r[1]), "=r"(r[2]), "=r"(r[3]) : "r"(addr));
}
__device__ __forceinline__ void mma16816(float c[4], const uint32_t a[4],
                                         uint32_t b0, uint32_t b1) {
    asm volatile(
        "mma.sync.aligned.m16n8k16.row.col.f32.bf16.bf16.f32 "
        "{%0,%1,%2,%3}, {%4,%5,%6,%7}, {%8,%9}, {%0,%1,%2,%3};"
        : "+f"(c[0]), "+f"(c[1]), "+f"(c[2]), "+f"(c[3])
        : "r"(a[0]), "r"(a[1]), "r"(a[2]), "r"(a[3]), "r"(b0), "r"(b1));
}
__device__ __forceinline__ void bsplit(float v, __nv_bfloat16& h, __nv_bfloat16& l) {
    h = __float2bfloat16(v);
    l = __float2bfloat16(v - __bfloat162float(h));
}

// ---------------- mma.sync split-bf16 GEMM ----------------
// C[M,N] = A[M,KA] (3rd K-segment remapped into [0,KA)) @ B[N,KB]^T (+bias)
// CTA tile 128x64, BK=32, 8 warps (32x32 warptiles), 3-stage cp.async pipeline.
// smem rows padded to 40 bf16 (80 B): ldmatrix 8-row reads cover all 32 banks.
#define ROWB 80                      // bytes per smem row (32 bf16 + 8 pad)
#define A_TILE_B (128 * ROWB)        // 10240
#define B_TILE_B (64 * ROWB)         // 5120

__global__ __launch_bounds__(256)
void gemm_mma(const __nv_bfloat16* __restrict__ A, const __nv_bfloat16* __restrict__ B,
              const float* __restrict__ bias, float* __restrict__ C,
              int M, int N, int KB, int KA) {
    __shared__ __align__(16) char sA[3 * A_TILE_B];
    __shared__ __align__(16) char sB[3 * B_TILE_B];

    const int tid = threadIdx.x;
    const int warp = tid >> 5, lane = tid & 31;
    const int m0 = blockIdx.x * 128;
    const int n0 = blockIdx.y * 64;
    const int wm = (warp >> 1) * 32;   // warp m offset in tile
    const int wn = (warp & 1) * 32;    // warp n offset in tile

    const uint32_t sAb = smem_u32(sA);
    const uint32_t sBb = smem_u32(sB);
    const int NK = KB / 32;

    float acc[2][4][4];
#pragma unroll
    for (int i = 0; i < 2; i++)
#pragma unroll
        for (int j = 0; j < 4; j++)
#pragma unroll
            for (int k = 0; k < 4; k++) acc[i][j][k] = 0.f;

    // ---- tile loader: tile `it` into buffer `it % 3` ----
    auto load_tile = [&](int it) {
        const int buf = it % 3;
        const int k0 = it * 32;
        const int ka = (k0 < KA) ? k0 : k0 - KA;   // 3rd B segment reuses A-hi
        const uint32_t aB = sAb + buf * A_TILE_B;
        const uint32_t bB = sBb + buf * B_TILE_B;
        // A: 128 rows x 4 16B segs = 512 cp16 (2/thread)
#pragma unroll
        for (int i = 0; i < 2; i++) {
            int idx = tid + i * 256;
            int row = idx >> 2, seg = idx & 3;
            cp16(aB + row * ROWB + seg * 16,
                 A + (size_t)(m0 + row) * KA + ka + seg * 8);
        }
        // B: 64 rows x 4 segs = 256 cp16 (1/thread)
        {
            int row = tid >> 2, seg = tid & 3;
            cp16(bB + row * ROWB + seg * 16,
                 B + (size_t)(n0 + row) * KB + k0 + seg * 8);
        }
        CP_COMMIT();
    };

    // prologue: 3 stages
    load_tile(0);
    if (NK > 1) load_tile(1);
    if (NK > 2) load_tile(2);

    for (int it = 0; it < NK; it++) {
        const int rem = NK - 1 - it;
        if (rem >= 2)      CP_WAIT(2);
        else if (rem == 1) CP_WAIT(1);
        else               CP_WAIT(0);
        __syncthreads();

        const int buf = it % 3;
        const uint32_t aB = sAb + buf * A_TILE_B;
        const uint32_t bB = sBb + buf * B_TILE_B;

#pragma unroll
        for (int ks = 0; ks < 2; ks++) {
            uint32_t ar[2][4], br[2][4];
#pragma unroll
            for (int mf = 0; mf < 2; mf++)
                ldsm4(ar[mf], aB + (wm + mf * 16 + (lane & 15)) * ROWB
                                 + (ks * 16 + (lane >> 4) * 8) * 2);
#pragma unroll
            for (int nf2 = 0; nf2 < 2; nf2++)
                ldsm4(br[nf2], bB + (wn + nf2 * 16 + (lane & 15)) * ROWB
                                  + (ks * 16 + (lane >> 4) * 8) * 2);
#pragma unroll
            for (int mf = 0; mf < 2; mf++)
#pragma unroll
                for (int nf = 0; nf < 4; nf++) {
                    uint32_t b0 = br[nf >> 1][(nf & 1) ? 1 : 0];
                    uint32_t b1 = br[nf >> 1][(nf & 1) ? 3 : 2];
                    mma16816(acc[mf][nf], ar[mf], b0, b1);
                }
        }
        __syncthreads();
        if (it + 3 < NK) load_tile(it + 3);
    }

    // ---- epilogue ----
    const bool hb = (bias != nullptr);
#pragma unroll
    for (int mf = 0; mf < 2; mf++)
#pragma unroll
        for (int nf = 0; nf < 4; nf++) {
            int row = m0 + wm + mf * 16 + (lane >> 2);
            int col = n0 + wn + nf * 8 + 2 * (lane & 3);
            float b0 = hb ? __ldg(&bias[col]) : 0.f;
            float b1 = hb ? __ldg(&bias[col + 1]) : 0.f;
            float2 v0 = make_float2(acc[mf][nf][0] + b0, acc[mf][nf][1] + b1);
            float2 v1 = make_float2(acc[mf][nf][2] + b0, acc[mf][nf][3] + b1);
            *(float2*)&C[(size_t)row * N + col] = v0;
            *(float2*)&C[(size_t)(row + 8) * N + col] = v1;
        }
}

// ---------------- split x into A1 = [hi|lo] ----------------
__global__ void split_x(const float* __restrict__ x, int n2) {  // n2 = M*512 float2s
    for (int j = blockIdx.x * blockDim.x + threadIdx.x; j < n2;
         j += gridDim.x * blockDim.x) {
        float2 v = ((const float2*)x)[j];
        int row = j >> 9;
        int col = (j & 511) << 1;
        __nv_bfloat16 hx, lx, hy, ly;
        bsplit(v.x, hx, lx); bsplit(v.y, hy, ly);
        size_t base = (size_t)row * 2048 + col;
        *(__nv_bfloat162*)&g_A1[base]        = __halves2bfloat162(hx, hy);
        *(__nv_bfloat162*)&g_A1[base + 1024] = __halves2bfloat162(lx, ly);
    }
}

// ---------------- pack weights ----------------
__global__ void pack_weights(const float* __restrict__ dw, const float* __restrict__ db,
                             const float* __restrict__ leaf, const float* __restrict__ gw,
                             const float* __restrict__ gb, const float* __restrict__ ntl) {
    int tid = blockIdx.x * blockDim.x + threadIdx.x;
    int stride = gridDim.x * blockDim.x;
    for (int i = tid; i < 240 * D_DIM; i += stride) {
        int n = i >> 10, d = i & 1023;
        __nv_bfloat16 h, l; bsplit(dw[i], h, l);
        size_t r = (size_t)n * 3072;
        g_B1[r + d] = h; g_B1[r + 1024 + d] = h; g_B1[r + 2048 + d] = l;
    }
    for (int i = tid; i < 16 * D_DIM; i += stride) {
        int t = i >> 10, d = i & 1023;
        __nv_bfloat16 h, l; bsplit(gw[d * 16 + t], h, l);
        size_t r = (size_t)(240 + t) * 3072;
        g_B1[r + d] = h; g_B1[r + 1024 + d] = h; g_B1[r + 2048 + d] = l;
    }
    for (int i = tid; i < O_DIM * 256; i += stride) {
        int o = i >> 8, k = i & 255;
        __nv_bfloat16 h, l; bsplit(leaf[(size_t)k * O_DIM + o], h, l);
        size_t r = (size_t)o * 768;
        g_B2[r + k] = h; g_B2[r + 256 + k] = h; g_B2[r + 512 + k] = l;
    }
    if (tid < 240) {
        g_bias[tid] = db[tid];
        float z = ntl[tid] + 0.5413f;
        float sp = (z > 20.f) ? z : log1pf(expf(z));
        g_invtemp[tid] = 1.0f / sp;
    } else if (tid < 256) {
        g_bias[tid] = gb[tid - 240];
    }
}

// ---------------- gate softmax + sigmoids + path products -> A2 ----------------
__global__ __launch_bounds__(256)
void build_w_kernel(int M) {
    int tok = (blockIdx.x * blockDim.x + threadIdx.x) >> 5;
    int lane = threadIdx.x & 31;
    if (tok >= M) return;
    const float* lrow = &g_logits[(size_t)tok * NCOLS];

    float gl = (lane < 16) ? lrow[240 + lane] : -INFINITY;
    float mx = gl;
#pragma unroll
    for (int o = 16; o > 0; o >>= 1) mx = fmaxf(mx, __shfl_xor_sync(0xffffffffu, mx, o));
    float e = (lane < 16) ? expf(gl - mx) : 0.f;
    float s = e;
#pragma unroll
    for (int o = 16; o > 0; o >>= 1) s += __shfl_xor_sync(0xffffffffu, s, o);
    float gate = e / s;

    if (lane < 16) {
        int t = lane;
        float dec[15];
#pragma unroll
        for (int n = 0; n < 15; n++) {
            float z = lrow[t * 15 + n] * g_invtemp[t * 15 + n];
            dec[n] = 1.f / (1.f + expf(-z));
        }
        size_t base = (size_t)tok * 512;
#pragma unroll
        for (int leaf = 0; leaf < 16; leaf++) {
            float p = gate;
            int node = 0;
#pragma unroll
            for (int d = 0; d < 4; d++) {
                int bit = (leaf >> (3 - d)) & 1;
                float dv = dec[node];
                p *= bit ? (1.f - dv) : dv;
                node = 2 * node + 1 + bit;
            }
            int k = t * 16 + leaf;
            __nv_bfloat16 h, l; bsplit(p, h, l);
            g_A2[base + k] = h;
            g_A2[base + 256 + k] = l;
        }
    }
}

// ---------------- in-place LayerNorm over O=512 ----------------
__global__ __launch_bounds__(256)
void layernorm_kernel(float* __restrict__ out, const float* __restrict__ gamma,
                      const float* __restrict__ beta, int M) {
    int tok = (blockIdx.x * blockDim.x + threadIdx.x) >> 5;
    int lane = threadIdx.x & 31;
    if (tok >= M) return;
    float* row = out + (size_t)tok * O_DIM;

    float v[16], s = 0.f, sq = 0.f;
#pragma unroll
    for (int i = 0; i < 16; i++) {
        v[i] = row[lane + 32 * i];
        s += v[i]; sq += v[i] * v[i];
    }
#pragma unroll
    for (int o = 16; o > 0; o >>= 1) {
        s  += __shfl_xor_sync(0xffffffffu, s, o);
        sq += __shfl_xor_sync(0xffffffffu, sq, o);
    }
    float mu = s * (1.f / O_DIM);
    float var = sq * (1.f / O_DIM) - mu * mu;
    float inv = rsqrtf(var + 1e-5f);
#pragma unroll
    for (int i = 0; i < 16; i++) {
        int c = lane + 32 * i;
        row[c] = (v[i] - mu) * inv * gamma[c] + beta[c];
    }
}

// ---------------- launch ----------------
extern "C" void kernel_launch(void* const* d_in, const int* in_sizes, int n_in,
                              void* d_out, int out_size) {
    const float* x     = (const float*)d_in[0];
    const float* dw    = (const float*)d_in[1];
    const float* db    = (const float*)d_in[2];
    const float* leaf  = (const float*)d_in[3];
    const float* gw    = (const float*)d_in[4];
    const float* gb    = (const float*)d_in[5];
    const float* ntl   = (const float*)d_in[6];
    const float* gamma = (const float*)d_in[7];
    const float* beta  = (const float*)d_in[8];
    float* out = (float*)d_out;

    int M = in_sizes[0] / D_DIM;   // 8192

    void *pA1, *pB1, *pA2, *pB2, *pLogits, *pBias;
    cudaGetSymbolAddress(&pA1, g_A1);
    cudaGetSymbolAddress(&pB1, g_B1);
    cudaGetSymbolAddress(&pA2, g_A2);
    cudaGetSymbolAddress(&pB2, g_B2);
    cudaGetSymbolAddress(&pLogits, g_logits);
    cudaGetSymbolAddress(&pBias, g_bias);

    // 0) conversions (independent)
    split_x<<<2048, 256>>>(x, M * 512);
    pack_weights<<<1024, 256>>>(dw, db, leaf, gw, gb, ntl);

    // 1) GEMM1: logits[M,256] = split(x) @ split(W)^T + bias   (K'=3072)
    gemm_mma<<<dim3(M / 128, NCOLS / 64), 256>>>(
        (const __nv_bfloat16*)pA1, (const __nv_bfloat16*)pB1,
        (const float*)pBias, (float*)pLogits, M, NCOLS, 3072, 2048);

    // 2) gate softmax + sigmoids + path products -> A2 (split)
    build_w_kernel<<<(M + 7) / 8, 256>>>(M);

    // 3) GEMM2: out[M,512] = split(Wl) @ split(leaf)^T   (K'=768)
    gemm_mma<<<dim3(M / 128, O_DIM / 64), 256>>>(
        (const __nv_bfloat16*)pA2, (const __nv_bfloat16*)pB2,
        nullptr, out, M, O_DIM, 768, 512);

    // 4) LayerNorm
    layernorm_kernel<<<(M + 7) / 8, 256>>>(out, gamma, beta, M);
}

// round 4
// speedup vs baseline: 1.7436x; 1.0878x over previous
#include <cuda_runtime.h>
#include <cuda_bf16.h>
#include <math.h>
#include <stdint.h>

// ---------------- problem constants ----------------
#define D_DIM 1024
#define NCOLS 256      // 240 decision + 16 gate logits
#define O_DIM 512
#define M_MAX 8192

// GEMM1: A = split(x) built in-kernel ([hi|lo|hi] over K'=3072), B1 [256,3072]=[hi|hi|lo]
// GEMM2: A2 [M,512]=[hi|lo] (from build_w), B2 [512,768]=[hi|hi|lo]
__device__ __align__(16) __nv_bfloat16 g_B1[NCOLS * 3072];
__device__ __align__(16) __nv_bfloat16 g_A2[M_MAX * 512];
__device__ __align__(16) __nv_bfloat16 g_B2[O_DIM * 768];
__device__ float g_logits[M_MAX * NCOLS];
__device__ float g_bias[NCOLS];
__device__ float g_invtemp[240];

// ---------------- helpers ----------------
__device__ __forceinline__ uint32_t smem_u32(const void* p) {
    uint32_t a;
    asm("{ .reg .u64 t; cvta.to.shared.u64 t, %1; cvt.u32.u64 %0, t; }"
        : "=r"(a) : "l"(p));
    return a;
}
__device__ __forceinline__ void cp16(uint32_t s, const void* g) {
    asm volatile("cp.async.cg.shared.global [%0], [%1], 16;" :: "r"(s), "l"(g));
}
#define CP_COMMIT() asm volatile("cp.async.commit_group;" ::: "memory")
#define CP_WAIT(n)  asm volatile("cp.async.wait_group %0;" :: "n"(n) : "memory")

__device__ __forceinline__ void ldsm4(uint32_t r[4], uint32_t addr) {
    asm volatile("ldmatrix.sync.aligned.m8n8.x4.shared.b16 {%0,%1,%2,%3}, [%4];"
                 : "=r"(r[0]), "=r"(r[1]), "=r"(r[2]), "=r"(r[3]) : "r"(addr));
}
__device__ __forceinline__ void mma16816(float c[4], const uint32_t a[4],
                                         uint32_t b0, uint32_t b1) {
    asm volatile(
        "mma.sync.aligned.m16n8k16.row.col.f32.bf16.bf16.f32 "
        "{%0,%1,%2,%3}, {%4,%5,%6,%7}, {%8,%9}, {%0,%1,%2,%3};"
        : "+f"(c[0]), "+f"(c[1]), "+f"(c[2]), "+f"(c[3])
        : "r"(a[0]), "r"(a[1]), "r"(a[2]), "r"(a[3]), "r"(b0), "r"(b1));
}
__device__ __forceinline__ void bsplit(float v, __nv_bfloat16& h, __nv_bfloat16& l) {
    h = __float2bfloat16(v);
    l = __float2bfloat16(v - __bfloat162float(h));
}

// smem geometry: rows padded to 80B (32 bf16 + 8 pad) -> conflict-free ldmatrix
#define ROWB   80
#define STAGE  (256 * ROWB)          // A(128 rows) + B(128 rows) = 20480 B
#define B_OFF  (128 * ROWB)
#define SMEM_BYTES (4 * STAGE)       // 81920

// ================= GEMM1: fused fp32-split A =================
// C[M,256] = split(x)[M,3072] @ B1[256,3072]^T + bias
__global__ __launch_bounds__(256)
void gemm1_fused(const float* __restrict__ x, const __nv_bfloat16* __restrict__ B1,
                 const float* __restrict__ bias, float* __restrict__ C, int M) {
    extern __shared__ char smem[];
    const uint32_t sb = smem_u32(smem);
    const int tid = threadIdx.x, warp = tid >> 5, lane = tid & 31;
    const int m0 = blockIdx.x * 128, n0 = blockIdx.y * 128;
    const int wm = (warp >> 1) * 32, wn = (warp & 1) * 64;
    const int NK = 96;                       // 3072/32
    const int arow = tid >> 1, ahalf = tid & 1;

    float acc[2][8][4];
#pragma unroll
    for (int i = 0; i < 2; i++)
#pragma unroll
        for (int j = 0; j < 8; j++)
#pragma unroll
            for (int k = 0; k < 4; k++) acc[i][j][k] = 0.f;

    float4 fv[4];
    auto ldgA = [&](int it) {
        if (it >= NK) return;
        int k0 = it * 32;
        int seg = k0 >> 10;                   // 0:hi 1:lo 2:hi
        int kx = (k0 & 1023) + ahalf * 16;
        const float* src = x + (size_t)(m0 + arow) * D_DIM + kx;
        fv[0] = *(const float4*)(src);
        fv[1] = *(const float4*)(src + 4);
        fv[2] = *(const float4*)(src + 8);
        fv[3] = *(const float4*)(src + 12);
        (void)seg;
    };
    auto stsA = [&](int it) {
        if (it >= NK) return;
        const bool lo = (((it * 32) >> 10) == 1);
        uint32_t dst = sb + (it & 3) * STAGE + arow * ROWB + ahalf * 32;
        uint32_t p[8];
        const float* f = (const float*)fv;
#pragma unroll
        for (int j = 0; j < 8; j++) {
            float v0 = f[2 * j], v1 = f[2 * j + 1];
            __nv_bfloat16 h0 = __float2bfloat16(v0), h1 = __float2bfloat16(v1);
            if (lo) {
                h0 = __float2bfloat16(v0 - __bfloat162float(h0));
                h1 = __float2bfloat16(v1 - __bfloat162float(h1));
            }
            __nv_bfloat162 t = __halves2bfloat162(h0, h1);
            p[j] = *(uint32_t*)&t;
        }
        asm volatile("st.shared.v4.b32 [%0], {%1,%2,%3,%4};"
                     :: "r"(dst), "r"(p[0]), "r"(p[1]), "r"(p[2]), "r"(p[3]));
        asm volatile("st.shared.v4.b32 [%0], {%1,%2,%3,%4};"
                     :: "r"(dst + 16), "r"(p[4]), "r"(p[5]), "r"(p[6]), "r"(p[7]));
    };
    auto cpB = [&](int it) {
        if (it < NK) {
            int k0 = it * 32;
            uint32_t bB = sb + (it & 3) * STAGE + B_OFF;
#pragma unroll
            for (int i = 0; i < 2; i++) {
                int idx = tid + i * 256;
                int row = idx >> 2, s = idx & 3;
                cp16(bB + row * ROWB + s * 16,
                     B1 + (size_t)(n0 + row) * 3072 + k0 + s * 8);
            }
        }
        CP_COMMIT();
    };

    // prologue: A tiles 0,1 in smem; B tiles 0..2 in flight
    ldgA(0); stsA(0);
    ldgA(1); stsA(1);
    cpB(0); cpB(1); cpB(2);

    for (int it = 0; it < NK; it++) {
        CP_WAIT(2);
        __syncthreads();
        ldgA(it + 2);          // stage fp32 for A tile it+2
        cpB(it + 3);           // async B tile it+3

        const uint32_t aB = sb + (it & 3) * STAGE;
        const uint32_t bB = aB + B_OFF;
#pragma unroll
        for (int ks = 0; ks < 2; ks++) {
            uint32_t ar[2][4], br[4][4];
            const uint32_t kb = (ks * 16 + (lane >> 4) * 8) * 2;
#pragma unroll
            for (int mf = 0; mf < 2; mf++)
                ldsm4(ar[mf], aB + (wm + mf * 16 + (lane & 15)) * ROWB + kb);
#pragma unroll
            for (int nf2 = 0; nf2 < 4; nf2++)
                ldsm4(br[nf2], bB + (wn + nf2 * 16 + (lane & 15)) * ROWB + kb);
#pragma unroll
            for (int mf = 0; mf < 2; mf++)
#pragma unroll
                for (int nf = 0; nf < 8; nf++) {
                    uint32_t b0 = br[nf >> 1][(nf & 1) ? 1 : 0];
                    uint32_t b1 = br[nf >> 1][(nf & 1) ? 3 : 2];
                    mma16816(acc[mf][nf], ar[mf], b0, b1);
                }
        }
        stsA(it + 2);          // convert + store A tile it+2
    }

    // epilogue (+bias)
#pragma unroll
    for (int mf = 0; mf < 2; mf++)
#pragma unroll
        for (int nf = 0; nf < 8; nf++) {
            int row = m0 + wm + mf * 16 + (lane >> 2);
            int col = n0 + wn + nf * 8 + 2 * (lane & 3);
            float b0 = __ldg(&bias[col]), b1 = __ldg(&bias[col + 1]);
            *(float2*)&C[(size_t)row * NCOLS + col] =
                make_float2(acc[mf][nf][0] + b0, acc[mf][nf][1] + b1);
            *(float2*)&C[(size_t)(row + 8) * NCOLS + col] =
                make_float2(acc[mf][nf][2] + b0, acc[mf][nf][3] + b1);
        }
}

// ================= GEMM2: both sides presplit bf16 =================
// C[M,N] = A[M,KA (remapped 3rd segment)] @ B[N,KB]^T
__global__ __launch_bounds__(256)
void gemm_bf16(const __nv_bfloat16* __restrict__ A, const __nv_bfloat16* __restrict__ B,
               float* __restrict__ C, int M, int N, int KB, int KA) {
    extern __shared__ char smem[];
    const uint32_t sb = smem_u32(smem);
    const int tid = threadIdx.x, warp = tid >> 5, lane = tid & 31;
    const int m0 = blockIdx.x * 128, n0 = blockIdx.y * 128;
    const int wm = (warp >> 1) * 32, wn = (warp & 1) * 64;
    const int NK = KB / 32;

    float acc[2][8][4];
#pragma unroll
    for (int i = 0; i < 2; i++)
#pragma unroll
        for (int j = 0; j < 8; j++)
#pragma unroll
            for (int k = 0; k < 4; k++) acc[i][j][k] = 0.f;

    auto cpAB = [&](int it) {
        if (it < NK) {
            int k0 = it * 32;
            int ka = (k0 < KA) ? k0 : k0 - KA;
            uint32_t aB = sb + (it & 3) * STAGE;
            uint32_t bB = aB + B_OFF;
#pragma unroll
            for (int i = 0; i < 2; i++) {
                int idx = tid + i * 256;
                int row = idx >> 2, s = idx & 3;
                cp16(aB + row * ROWB + s * 16,
                     A + (size_t)(m0 + row) * KA + ka + s * 8);
                cp16(bB + row * ROWB + s * 16,
                     B + (size_t)(n0 + row) * KB + k0 + s * 8);
            }
        }
        CP_COMMIT();
    };

    cpAB(0); cpAB(1); cpAB(2);

    for (int it = 0; it < NK; it++) {
        CP_WAIT(2);
        __syncthreads();
        cpAB(it + 3);

        const uint32_t aB = sb + (it & 3) * STAGE;
        const uint32_t bB = aB + B_OFF;
#pragma unroll
        for (int ks = 0; ks < 2; ks++) {
            uint32_t ar[2][4], br[4][4];
            const uint32_t kb = (ks * 16 + (lane >> 4) * 8) * 2;
#pragma unroll
            for (int mf = 0; mf < 2; mf++)
                ldsm4(ar[mf], aB + (wm + mf * 16 + (lane & 15)) * ROWB + kb);
#pragma unroll
            for (int nf2 = 0; nf2 < 4; nf2++)
                ldsm4(br[nf2], bB + (wn + nf2 * 16 + (lane & 15)) * ROWB + kb);
#pragma unroll
            for (int mf = 0; mf < 2; mf++)
#pragma unroll
                for (int nf = 0; nf < 8; nf++) {
                    uint32_t b0 = br[nf >> 1][(nf & 1) ? 1 : 0];
                    uint32_t b1 = br[nf >> 1][(nf & 1) ? 3 : 2];
                    mma16816(acc[mf][nf], ar[mf], b0, b1);
                }
        }
    }

#pragma unroll
    for (int mf = 0; mf < 2; mf++)
#pragma unroll
        for (int nf = 0; nf < 8; nf++) {
            int row = m0 + wm + mf * 16 + (lane >> 2);
            int col = n0 + wn + nf * 8 + 2 * (lane & 3);
            *(float2*)&C[(size_t)row * N + col] =
                make_float2(acc[mf][nf][0], acc[mf][nf][1]);
            *(float2*)&C[(size_t)(row + 8) * N + col] =
                make_float2(acc[mf][nf][2], acc[mf][nf][3]);
        }
}

// ---------------- pack weights ----------------
__global__ void pack_weights(const float* __restrict__ dw, const float* __restrict__ db,
                             const float* __restrict__ leaf, const float* __restrict__ gw,
                             const float* __restrict__ gb, const float* __restrict__ ntl) {
    int tid = blockIdx.x * blockDim.x + threadIdx.x;
    int stride = gridDim.x * blockDim.x;
    for (int i = tid; i < 240 * D_DIM; i += stride) {
        int n = i >> 10, d = i & 1023;
        __nv_bfloat16 h, l; bsplit(dw[i], h, l);
        size_t r = (size_t)n * 3072;
        g_B1[r + d] = h; g_B1[r + 1024 + d] = h; g_B1[r + 2048 + d] = l;
    }
    for (int i = tid; i < 16 * D_DIM; i += stride) {
        int t = i >> 10, d = i & 1023;
        __nv_bfloat16 h, l; bsplit(gw[d * 16 + t], h, l);
        size_t r = (size_t)(240 + t) * 3072;
        g_B1[r + d] = h; g_B1[r + 1024 + d] = h; g_B1[r + 2048 + d] = l;
    }
    for (int i = tid; i < O_DIM * 256; i += stride) {
        int o = i >> 8, k = i & 255;
        __nv_bfloat16 h, l; bsplit(leaf[(size_t)k * O_DIM + o], h, l);
        size_t r = (size_t)o * 768;
        g_B2[r + k] = h; g_B2[r + 256 + k] = h; g_B2[r + 512 + k] = l;
    }
    if (tid < 240) {
        g_bias[tid] = db[tid];
        float z = ntl[tid] + 0.5413f;
        float sp = (z > 20.f) ? z : log1pf(expf(z));
        g_invtemp[tid] = 1.0f / sp;
    } else if (tid < 256) {
        g_bias[tid] = gb[tid - 240];
    }
}

// ---------------- gate softmax + sigmoids + path products -> A2 ----------------
__global__ __launch_bounds__(256)
void build_w_kernel(int M) {
    __shared__ float sl[8][256];
    int w = threadIdx.x >> 5;
    int lane = threadIdx.x & 31;
    int tok = blockIdx.x * 8 + w;
    if (tok >= M) return;

    // coalesced staged load of this token's 256 logits
    const float4* src = (const float4*)&g_logits[(size_t)tok * NCOLS];
    float4* dst4 = (float4*)sl[w];
    dst4[lane] = src[lane];
    dst4[lane + 32] = src[lane + 32];
    __syncwarp();
    const float* lrow = sl[w];

    float gl = (lane < 16) ? lrow[240 + lane] : -INFINITY;
    float mx = gl;
#pragma unroll
    for (int o = 16; o > 0; o >>= 1) mx = fmaxf(mx, __shfl_xor_sync(0xffffffffu, mx, o));
    float e = (lane < 16) ? expf(gl - mx) : 0.f;
    float s = e;
#pragma unroll
    for (int o = 16; o > 0; o >>= 1) s += __shfl_xor_sync(0xffffffffu, s, o);
    float gate = e / s;

    if (lane < 16) {
        int t = lane;
        float dec[15];
#pragma unroll
        for (int n = 0; n < 15; n++) {
            float z = lrow[t * 15 + n] * g_invtemp[t * 15 + n];
            dec[n] = 1.f / (1.f + expf(-z));
        }
        __nv_bfloat162 hi[8], lo[8];
#pragma unroll
        for (int leaf = 0; leaf < 16; leaf += 2) {
            __nv_bfloat16 h[2], l[2];
#pragma unroll
            for (int q = 0; q < 2; q++) {
                int lf = leaf + q;
                float p = gate;
                int node = 0;
#pragma unroll
                for (int d = 0; d < 4; d++) {
                    int bit = (lf >> (3 - d)) & 1;
                    float dv = dec[node];
                    p *= bit ? (1.f - dv) : dv;
                    node = 2 * node + 1 + bit;
                }
                bsplit(p, h[q], l[q]);
            }
            hi[leaf >> 1] = __halves2bfloat162(h[0], h[1]);
            lo[leaf >> 1] = __halves2bfloat162(l[0], l[1]);
        }
        size_t base = (size_t)tok * 512 + t * 16;
        *(uint4*)&g_A2[base]       = ((uint4*)hi)[0];
        *(uint4*)&g_A2[base + 8]   = ((uint4*)hi)[1];
        *(uint4*)&g_A2[base + 256] = ((uint4*)lo)[0];
        *(uint4*)&g_A2[base + 264] = ((uint4*)lo)[1];
    }
}

// ---------------- in-place LayerNorm over O=512 ----------------
__global__ __launch_bounds__(256)
void layernorm_kernel(float* __restrict__ out, const float* __restrict__ gamma,
                      const float* __restrict__ beta, int M) {
    int tok = (blockIdx.x * blockDim.x + threadIdx.x) >> 5;
    int lane = threadIdx.x & 31;
    if (tok >= M) return;
    float* row = out + (size_t)tok * O_DIM;

    float v[16], s = 0.f, sq = 0.f;
#pragma unroll
    for (int i = 0; i < 16; i++) {
        v[i] = row[lane + 32 * i];
        s += v[i]; sq += v[i] * v[i];
    }
#pragma unroll
    for (int o = 16; o > 0; o >>= 1) {
        s  += __shfl_xor_sync(0xffffffffu, s, o);
        sq += __shfl_xor_sync(0xffffffffu, sq, o);
    }
    float mu = s * (1.f / O_DIM);
    float var = sq * (1.f / O_DIM) - mu * mu;
    float inv = rsqrtf(var + 1e-5f);
#pragma unroll
    for (int i = 0; i < 16; i++) {
        int c = lane + 32 * i;
        row[c] = (v[i] - mu) * inv * gamma[c] + beta[c];
    }
}

// ---------------- launch ----------------
extern "C" void kernel_launch(void* const* d_in, const int* in_sizes, int n_in,
                              void* d_out, int out_size) {
    const float* x     = (const float*)d_in[0];
    const float* dw    = (const float*)d_in[1];
    const float* db    = (const float*)d_in[2];
    const float* leaf  = (const float*)d_in[3];
    const float* gw    = (const float*)d_in[4];
    const float* gb    = (const float*)d_in[5];
    const float* ntl   = (const float*)d_in[6];
    const float* gamma = (const float*)d_in[7];
    const float* beta  = (const float*)d_in[8];
    float* out = (float*)d_out;

    int M = in_sizes[0] / D_DIM;   // 8192

    void *pB1, *pA2, *pB2, *pLogits, *pBias;
    cudaGetSymbolAddress(&pB1, g_B1);
    cudaGetSymbolAddress(&pA2, g_A2);
    cudaGetSymbolAddress(&pB2, g_B2);
    cudaGetSymbolAddress(&pLogits, g_logits);
    cudaGetSymbolAddress(&pBias, g_bias);

    static bool attr_set = false;
    if (!attr_set) {
        cudaFuncSetAttribute(gemm1_fused, cudaFuncAttributeMaxDynamicSharedMemorySize,
                             SMEM_BYTES);
        cudaFuncSetAttribute(gemm_bf16, cudaFuncAttributeMaxDynamicSharedMemorySize,
                             SMEM_BYTES);
        attr_set = true;
    }

    // 0) weight packing (small)
    pack_weights<<<1024, 256>>>(dw, db, leaf, gw, gb, ntl);

    // 1) GEMM1 (fused split of x): logits[M,256], K'=3072
    gemm1_fused<<<dim3(M / 128, 2), 256, SMEM_BYTES>>>(
        x, (const __nv_bfloat16*)pB1, (const float*)pBias, (float*)pLogits, M);

    // 2) gate softmax + sigmoids + path products -> A2 (split)
    build_w_kernel<<<M / 8, 256>>>(M);

    // 3) GEMM2: out[M,512] = split(Wl) @ split(leaf)^T, K'=768
    gemm_bf16<<<dim3(M / 128, 4), 256, SMEM_BYTES>>>(
        (const __nv_bfloat16*)pA2, (const __nv_bfloat16*)pB2, out, M, O_DIM, 768, 512);

    // 4) LayerNorm
    layernorm_kernel<<<M / 8, 256>>>(out, gamma, beta, M);
}

// round 5
// speedup vs baseline: 1.7755x; 1.0183x over previous
#include <cuda_runtime.h>
#include <cuda_bf16.h>
#include <math.h>
#include <stdint.h>

// ---------------- problem constants ----------------
#define D_DIM 1024
#define NCOLS 256      // 240 decision + 16 gate logits
#define O_DIM 512
#define M_MAX 8192

// GEMM1: A = split(x) fused in-kernel ([hi|lo|hi] over K'=3072), B1 [256,3072]=[hi|hi|lo]
// GEMM2: A2 [M,512]=[hi|lo], B2 [512,768]=[hi|hi|lo]
__device__ __align__(16) __nv_bfloat16 g_B1[NCOLS * 3072];
__device__ __align__(16) __nv_bfloat16 g_A2[M_MAX * 512];
__device__ __align__(16) __nv_bfloat16 g_B2[O_DIM * 768];
__device__ __align__(16) float g_logits[2 * M_MAX * NCOLS];   // split-K partials
__device__ __align__(16) float g_bias[NCOLS];
__device__ float g_invtemp[240];

// ---------------- helpers ----------------
__device__ __forceinline__ uint32_t smem_u32(const void* p) {
    uint32_t a;
    asm("{ .reg .u64 t; cvta.to.shared.u64 t, %1; cvt.u32.u64 %0, t; }"
        : "=r"(a) : "l"(p));
    return a;
}
__device__ __forceinline__ void cp16(uint32_t s, const void* g) {
    asm volatile("cp.async.cg.shared.global [%0], [%1], 16;" :: "r"(s), "l"(g));
}
#define CP_COMMIT() asm volatile("cp.async.commit_group;" ::: "memory")
#define CP_WAIT(n)  asm volatile("cp.async.wait_group %0;" :: "n"(n) : "memory")

__device__ __forceinline__ void ldsm4(uint32_t r[4], uint32_t addr) {
    asm volatile("ldmatrix.sync.aligned.m8n8.x4.shared.b16 {%0,%1,%2,%3}, [%4];"
                 : "=r"(r[0]), "=r"(r[1]), "=r"(r[2]), "=r"(r[3]) : "r"(addr));
}
__device__ __forceinline__ void mma16816(float c[4], const uint32_t a[4],
                                         uint32_t b0, uint32_t b1) {
    asm volatile(
        "mma.sync.aligned.m16n8k16.row.col.f32.bf16.bf16.f32 "
        "{%0,%1,%2,%3}, {%4,%5,%6,%7}, {%8,%9}, {%0,%1,%2,%3};"
        : "+f"(c[0]), "+f"(c[1]), "+f"(c[2]), "+f"(c[3])
        : "r"(a[0]), "r"(a[1]), "r"(a[2]), "r"(a[3]), "r"(b0), "r"(b1));
}
__device__ __forceinline__ void bsplit(float v, __nv_bfloat16& h, __nv_bfloat16& l) {
    h = __float2bfloat16(v);
    l = __float2bfloat16(v - __bfloat162float(h));
}

// smem geometry: rows padded to 80 B (32 bf16 + 8 pad) -> conflict-free ldmatrix
#define ROWB   80
#define STAGE  (256 * ROWB)          // A(128 rows) + B(128 rows) = 20480 B
#define B_OFF  (128 * ROWB)
#define SMEM_BYTES (4 * STAGE)       // 81920

// 512 threads = 16 warps, 4x4 warptiles of 32x32 over the 128x128 CTA tile.
// Inner compute shared by both GEMMs.
#define COMPUTE_TILE(aB, bB)                                                      \
    do {                                                                          \
        _Pragma("unroll")                                                         \
        for (int ks = 0; ks < 2; ks++) {                                          \
            uint32_t ar[2][4], br[2][4];                                          \
            const uint32_t kb = (ks * 16 + (lane >> 4) * 8) * 2;                  \
            _Pragma("unroll")                                                     \
            for (int mf = 0; mf < 2; mf++)                                        \
                ldsm4(ar[mf], (aB) + (wm + mf * 16 + (lane & 15)) * ROWB + kb);   \
            _Pragma("unroll")                                                     \
            for (int nf2 = 0; nf2 < 2; nf2++)                                     \
                ldsm4(br[nf2], (bB) + (wn + nf2 * 16 + (lane & 15)) * ROWB + kb); \
            _Pragma("unroll")                                                     \
            for (int mf = 0; mf < 2; mf++)                                        \
                _Pragma("unroll")                                                 \
                for (int nf = 0; nf < 4; nf++) {                                  \
                    uint32_t b0 = br[nf >> 1][(nf & 1) ? 1 : 0];                  \
                    uint32_t b1 = br[nf >> 1][(nf & 1) ? 3 : 2];                  \
                    mma16816(acc[mf][nf], ar[mf], b0, b1);                        \
                }                                                                 \
        }                                                                         \
    } while (0)

// ================= GEMM1: fused fp32-split A, split-K=2 =================
// Cpart[M,256] = split(x)[M, koff..koff+1536] @ B1[256, same]^T  (no bias here)
__global__ __launch_bounds__(512)
void gemm1_fused(const float* __restrict__ x, const __nv_bfloat16* __restrict__ B1,
                 float* __restrict__ Cbase, int M) {
    extern __shared__ char smem[];
    const uint32_t sb = smem_u32(smem);
    const int tid = threadIdx.x, warp = tid >> 5, lane = tid & 31;
    const int m0 = blockIdx.x * 128, n0 = blockIdx.y * 128;
    const int koff = blockIdx.z * 1536;
    float* C = Cbase + (size_t)blockIdx.z * M * NCOLS;
    const int wm = (warp >> 2) * 32, wn = (warp & 3) * 32;
    const int NK = 48;                        // 1536/32
    const int arow = tid >> 2, aq = tid & 3;  // A loader: row 0..127, 8-float quarter

    float acc[2][4][4];
#pragma unroll
    for (int i = 0; i < 2; i++)
#pragma unroll
        for (int j = 0; j < 4; j++)
#pragma unroll
            for (int k = 0; k < 4; k++) acc[i][j][k] = 0.f;

    float4 fv[2];
    auto ldgA = [&](int it) {
        if (it >= NK) return;
        int k0 = koff + it * 32;
        int xa = (k0 & 1023) + aq * 8;
        const float* src = x + (size_t)(m0 + arow) * D_DIM + xa;
        fv[0] = *(const float4*)(src);
        fv[1] = *(const float4*)(src + 4);
    };
    auto stsA = [&](int it) {
        if (it >= NK) return;
        int k0 = koff + it * 32;
        const bool lo = ((k0 >> 10) == 1);
        uint32_t dst = sb + (it & 3) * STAGE + arow * ROWB + aq * 16;
        uint32_t p[4];
        const float* f = (const float*)fv;
#pragma unroll
        for (int j = 0; j < 4; j++) {
            float v0 = f[2 * j], v1 = f[2 * j + 1];
            __nv_bfloat16 h0 = __float2bfloat16(v0), h1 = __float2bfloat16(v1);
            if (lo) {
                h0 = __float2bfloat16(v0 - __bfloat162float(h0));
                h1 = __float2bfloat16(v1 - __bfloat162float(h1));
            }
            __nv_bfloat162 t = __halves2bfloat162(h0, h1);
            p[j] = *(uint32_t*)&t;
        }
        asm volatile("st.shared.v4.b32 [%0], {%1,%2,%3,%4};"
                     :: "r"(dst), "r"(p[0]), "r"(p[1]), "r"(p[2]), "r"(p[3]));
    };
    auto cpB = [&](int it) {
        if (it < NK) {
            int k0 = koff + it * 32;
            uint32_t bB = sb + (it & 3) * STAGE + B_OFF;
            int row = tid >> 2, s = tid & 3;
            cp16(bB + row * ROWB + s * 16, B1 + (size_t)(n0 + row) * 3072 + k0 + s * 8);
        }
        CP_COMMIT();
    };

    ldgA(0); stsA(0);
    ldgA(1); stsA(1);
    cpB(0); cpB(1); cpB(2);

    for (int it = 0; it < NK; it++) {
        CP_WAIT(2);
        __syncthreads();
        ldgA(it + 2);
        cpB(it + 3);
        const uint32_t aB = sb + (it & 3) * STAGE;
        COMPUTE_TILE(aB, aB + B_OFF);
        stsA(it + 2);
    }

#pragma unroll
    for (int mf = 0; mf < 2; mf++)
#pragma unroll
        for (int nf = 0; nf < 4; nf++) {
            int row = m0 + wm + mf * 16 + (lane >> 2);
            int col = n0 + wn + nf * 8 + 2 * (lane & 3);
            *(float2*)&C[(size_t)row * NCOLS + col] =
                make_float2(acc[mf][nf][0], acc[mf][nf][1]);
            *(float2*)&C[(size_t)(row + 8) * NCOLS + col] =
                make_float2(acc[mf][nf][2], acc[mf][nf][3]);
        }
}

// ================= GEMM2: both sides presplit bf16 =================
__global__ __launch_bounds__(512)
void gemm_bf16(const __nv_bfloat16* __restrict__ A, const __nv_bfloat16* __restrict__ B,
               float* __restrict__ C, int M, int N, int KB, int KA) {
    extern __shared__ char smem[];
    const uint32_t sb = smem_u32(smem);
    const int tid = threadIdx.x, warp = tid >> 5, lane = tid & 31;
    const int m0 = blockIdx.x * 128, n0 = blockIdx.y * 128;
    const int wm = (warp >> 2) * 32, wn = (warp & 3) * 32;
    const int NK = KB / 32;

    float acc[2][4][4];
#pragma unroll
    for (int i = 0; i < 2; i++)
#pragma unroll
        for (int j = 0; j < 4; j++)
#pragma unroll
            for (int k = 0; k < 4; k++) acc[i][j][k] = 0.f;

    auto cpAB = [&](int it) {
        if (it < NK) {
            int k0 = it * 32;
            int ka = (k0 < KA) ? k0 : k0 - KA;
            uint32_t aB = sb + (it & 3) * STAGE;
            uint32_t bB = aB + B_OFF;
            int row = tid >> 2, s = tid & 3;
            cp16(aB + row * ROWB + s * 16, A + (size_t)(m0 + row) * KA + ka + s * 8);
            cp16(bB + row * ROWB + s * 16, B + (size_t)(n0 + row) * KB + k0 + s * 8);
        }
        CP_COMMIT();
    };

    cpAB(0); cpAB(1); cpAB(2);

    for (int it = 0; it < NK; it++) {
        CP_WAIT(2);
        __syncthreads();
        cpAB(it + 3);
        const uint32_t aB = sb + (it & 3) * STAGE;
        COMPUTE_TILE(aB, aB + B_OFF);
    }

#pragma unroll
    for (int mf = 0; mf < 2; mf++)
#pragma unroll
        for (int nf = 0; nf < 4; nf++) {
            int row = m0 + wm + mf * 16 + (lane >> 2);
            int col = n0 + wn + nf * 8 + 2 * (lane & 3);
            *(float2*)&C[(size_t)row * N + col] =
                make_float2(acc[mf][nf][0], acc[mf][nf][1]);
            *(float2*)&C[(size_t)(row + 8) * N + col] =
                make_float2(acc[mf][nf][2], acc[mf][nf][3]);
        }
}

// ---------------- pack weights ----------------
__global__ void pack_weights(const float* __restrict__ dw, const float* __restrict__ db,
                             const float* __restrict__ leaf, const float* __restrict__ gw,
                             const float* __restrict__ gb, const float* __restrict__ ntl) {
    int tid = blockIdx.x * blockDim.x + threadIdx.x;
    int stride = gridDim.x * blockDim.x;
    for (int i = tid; i < 240 * D_DIM; i += stride) {
        int n = i >> 10, d = i & 1023;
        __nv_bfloat16 h, l; bsplit(dw[i], h, l);
        size_t r = (size_t)n * 3072;
        g_B1[r + d] = h; g_B1[r + 1024 + d] = h; g_B1[r + 2048 + d] = l;
    }
    for (int i = tid; i < 16 * D_DIM; i += stride) {
        int t = i >> 10, d = i & 1023;
        __nv_bfloat16 h, l; bsplit(gw[d * 16 + t], h, l);
        size_t r = (size_t)(240 + t) * 3072;
        g_B1[r + d] = h; g_B1[r + 1024 + d] = h; g_B1[r + 2048 + d] = l;
    }
    for (int i = tid; i < O_DIM * 256; i += stride) {
        int o = i >> 8, k = i & 255;
        __nv_bfloat16 h, l; bsplit(leaf[(size_t)k * O_DIM + o], h, l);
        size_t r = (size_t)o * 768;
        g_B2[r + k] = h; g_B2[r + 256 + k] = h; g_B2[r + 512 + k] = l;
    }
    if (tid < 240) {
        g_bias[tid] = db[tid];
        float z = ntl[tid] + 0.5413f;
        float sp = (z > 20.f) ? z : log1pf(expf(z));
        g_invtemp[tid] = 1.0f / sp;
    } else if (tid < 256) {
        g_bias[tid] = gb[tid - 240];
    }
}

// ------- combine split-K partials + bias, gate softmax, path products -> A2 -------
__global__ __launch_bounds__(256)
void build_w_kernel(int M) {
    __shared__ float sl[8][256];
    int w = threadIdx.x >> 5;
    int lane = threadIdx.x & 31;
    int tok = blockIdx.x * 8 + w;
    if (tok >= M) return;

    // coalesced staged load: logits = partial0 + partial1 + bias
    const float4* s0 = (const float4*)&g_logits[(size_t)tok * NCOLS];
    const float4* s1 = (const float4*)&g_logits[(size_t)(M + tok) * NCOLS];
    const float4* bb = (const float4*)g_bias;
    float4* dst4 = (float4*)sl[w];
#pragma unroll
    for (int i = 0; i < 2; i++) {
        int j = lane + 32 * i;
        float4 a = s0[j], b = s1[j], c = bb[j];
        dst4[j] = make_float4(a.x + b.x + c.x, a.y + b.y + c.y,
                              a.z + b.z + c.z, a.w + b.w + c.w);
    }
    __syncwarp();
    const float* lrow = sl[w];

    float gl = (lane < 16) ? lrow[240 + lane] : -INFINITY;
    float mx = gl;
#pragma unroll
    for (int o = 16; o > 0; o >>= 1) mx = fmaxf(mx, __shfl_xor_sync(0xffffffffu, mx, o));
    float e = (lane < 16) ? expf(gl - mx) : 0.f;
    float s = e;
#pragma unroll
    for (int o = 16; o > 0; o >>= 1) s += __shfl_xor_sync(0xffffffffu, s, o);
    float gate = e / s;

    if (lane < 16) {
        int t = lane;
        float dec[15];
#pragma unroll
        for (int n = 0; n < 15; n++) {
            float z = lrow[t * 15 + n] * g_invtemp[t * 15 + n];
            dec[n] = 1.f / (1.f + expf(-z));
        }
        __nv_bfloat162 hi[8], lo[8];
#pragma unroll
        for (int leaf = 0; leaf < 16; leaf += 2) {
            __nv_bfloat16 h[2], l[2];
#pragma unroll
            for (int q = 0; q < 2; q++) {
                int lf = leaf + q;
                float p = gate;
                int node = 0;
#pragma unroll
                for (int d = 0; d < 4; d++) {
                    int bit = (lf >> (3 - d)) & 1;
                    float dv = dec[node];
                    p *= bit ? (1.f - dv) : dv;
                    node = 2 * node + 1 + bit;
                }
                bsplit(p, h[q], l[q]);
            }
            hi[leaf >> 1] = __halves2bfloat162(h[0], h[1]);
            lo[leaf >> 1] = __halves2bfloat162(l[0], l[1]);
        }
        size_t base = (size_t)tok * 512 + t * 16;
        *(uint4*)&g_A2[base]       = ((uint4*)hi)[0];
        *(uint4*)&g_A2[base + 8]   = ((uint4*)hi)[1];
        *(uint4*)&g_A2[base + 256] = ((uint4*)lo)[0];
        *(uint4*)&g_A2[base + 264] = ((uint4*)lo)[1];
    }
}

// ---------------- in-place LayerNorm over O=512 ----------------
__global__ __launch_bounds__(256)
void layernorm_kernel(float* __restrict__ out, const float* __restrict__ gamma,
                      const float* __restrict__ beta, int M) {
    int tok = (blockIdx.x * blockDim.x + threadIdx.x) >> 5;
    int lane = threadIdx.x & 31;
    if (tok >= M) return;
    float* row = out + (size_t)tok * O_DIM;

    float v[16], s = 0.f, sq = 0.f;
#pragma unroll
    for (int i = 0; i < 16; i++) {
        v[i] = row[lane + 32 * i];
        s += v[i]; sq += v[i] * v[i];
    }
#pragma unroll
    for (int o = 16; o > 0; o >>= 1) {
        s  += __shfl_xor_sync(0xffffffffu, s, o);
        sq += __shfl_xor_sync(0xffffffffu, sq, o);
    }
    float mu = s * (1.f / O_DIM);
    float var = sq * (1.f / O_DIM) - mu * mu;
    float inv = rsqrtf(var + 1e-5f);
#pragma unroll
    for (int i = 0; i < 16; i++) {
        int c = lane + 32 * i;
        row[c] = (v[i] - mu) * inv * gamma[c] + beta[c];
    }
}

// ---------------- launch ----------------
extern "C" void kernel_launch(void* const* d_in, const int* in_sizes, int n_in,
                              void* d_out, int out_size) {
    const float* x     = (const float*)d_in[0];
    const float* dw    = (const float*)d_in[1];
    const float* db    = (const float*)d_in[2];
    const float* leaf  = (const float*)d_in[3];
    const float* gw    = (const float*)d_in[4];
    const float* gb    = (const float*)d_in[5];
    const float* ntl   = (const float*)d_in[6];
    const float* gamma = (const float*)d_in[7];
    const float* beta  = (const float*)d_in[8];
    float* out = (float*)d_out;

    int M = in_sizes[0] / D_DIM;   // 8192

    void *pB1, *pA2, *pB2, *pLogits;
    cudaGetSymbolAddress(&pB1, g_B1);
    cudaGetSymbolAddress(&pA2, g_A2);
    cudaGetSymbolAddress(&pB2, g_B2);
    cudaGetSymbolAddress(&pLogits, g_logits);

    static bool attr_set = false;
    if (!attr_set) {
        cudaFuncSetAttribute(gemm1_fused, cudaFuncAttributeMaxDynamicSharedMemorySize,
                             SMEM_BYTES);
        cudaFuncSetAttribute(gemm_bf16, cudaFuncAttributeMaxDynamicSharedMemorySize,
                             SMEM_BYTES);
        attr_set = true;
    }

    // 0) weight packing (small)
    pack_weights<<<1024, 256>>>(dw, db, leaf, gw, gb, ntl);

    // 1) GEMM1 (fused split of x), split-K=2: partials[2][M,256]
    gemm1_fused<<<dim3(M / 128, 2, 2), 512, SMEM_BYTES>>>(
        x, (const __nv_bfloat16*)pB1, (float*)pLogits, M);

    // 2) combine partials + bias, gate softmax, path products -> A2 (split)
    build_w_kernel<<<M / 8, 256>>>(M);

    // 3) GEMM2: out[M,512] = split(Wl) @ split(leaf)^T, K'=768
    gemm_bf16<<<dim3(M / 128, 4), 512, SMEM_BYTES>>>(
        (const __nv_bfloat16*)pA2, (const __nv_bfloat16*)pB2, out, M, O_DIM, 768, 512);

    // 4) LayerNorm
    layernorm_kernel<<<M / 8, 256>>>(out, gamma, beta, M);
}

// round 6
// speedup vs baseline: 2.1574x; 1.2151x over previous
#include <cuda_runtime.h>
#include <cuda_bf16.h>
#include <math.h>
#include <stdint.h>

// ---------------- problem constants ----------------
#define D_DIM 1024
#define NCOLS 256      // 240 decision + 16 gate logits
#define O_DIM 512
#define M_MAX 8192

// GEMM1: B1 [256, 2048] = [hi|lo] (x split fused in-kernel)
// GEMM2: A2 [M,512]=[hi|lo], B2 [512,768]=[hi|hi|lo]
__device__ __align__(16) __nv_bfloat16 g_B1[NCOLS * 2048];
__device__ __align__(16) __nv_bfloat16 g_A2[M_MAX * 512];
__device__ __align__(16) __nv_bfloat16 g_B2[O_DIM * 768];
__device__ __align__(16) float g_logits[2 * M_MAX * NCOLS];   // split-K partials
__device__ __align__(16) float g_bias[NCOLS];
__device__ float g_invtemp[240];

// ---------------- helpers ----------------
__device__ __forceinline__ uint32_t smem_u32(const void* p) {
    uint32_t a;
    asm("{ .reg .u64 t; cvta.to.shared.u64 t, %1; cvt.u32.u64 %0, t; }"
        : "=r"(a) : "l"(p));
    return a;
}
__device__ __forceinline__ void cp16(uint32_t s, const void* g) {
    asm volatile("cp.async.cg.shared.global [%0], [%1], 16;" :: "r"(s), "l"(g));
}
#define CP_COMMIT() asm volatile("cp.async.commit_group;" ::: "memory")
#define CP_WAIT(n)  asm volatile("cp.async.wait_group %0;" :: "n"(n) : "memory")

__device__ __forceinline__ void ldsm4(uint32_t r[4], uint32_t addr) {
    asm volatile("ldmatrix.sync.aligned.m8n8.x4.shared.b16 {%0,%1,%2,%3}, [%4];"
                 : "=r"(r[0]), "=r"(r[1]), "=r"(r[2]), "=r"(r[3]) : "r"(addr));
}
__device__ __forceinline__ void mma16816(float c[4], const uint32_t a[4],
                                         uint32_t b0, uint32_t b1) {
    asm volatile(
        "mma.sync.aligned.m16n8k16.row.col.f32.bf16.bf16.f32 "
        "{%0,%1,%2,%3}, {%4,%5,%6,%7}, {%8,%9}, {%0,%1,%2,%3};"
        : "+f"(c[0]), "+f"(c[1]), "+f"(c[2]), "+f"(c[3])
        : "r"(a[0]), "r"(a[1]), "r"(a[2]), "r"(a[3]), "r"(b0), "r"(b1));
}
__device__ __forceinline__ void bsplit(float v, __nv_bfloat16& h, __nv_bfloat16& l) {
    h = __float2bfloat16(v);
    l = __float2bfloat16(v - __bfloat162float(h));
}

// ================= GEMM1: fused-split x, hi/lo shared-tile 3-term =================
// partial[M,256] = sum over real-k chunk of (ah*bh + al*bh + ah*bl)
// CTA 128x128, 512 thr (16 warps, 32x32 warptiles), BK=32 real-k, 3 stages.
#define ROWB1  80                     // 32 bf16 + 8 B pad
#define T1     (128 * ROWB1)          // one tile: 10240 B
#define AL_OFF (1 * T1)
#define BH_OFF (2 * T1)
#define BL_OFF (3 * T1)
#define STAGE1 (4 * T1)               // 40960 B
#define SMEM1  (3 * STAGE1)           // 122880 B

__global__ __launch_bounds__(512)
void gemm1_fused(const float* __restrict__ x, const __nv_bfloat16* __restrict__ B1,
                 float* __restrict__ Cbase, int M) {
    extern __shared__ char smem[];
    const uint32_t sb = smem_u32(smem);
    const int tid = threadIdx.x, warp = tid >> 5, lane = tid & 31;
    const int m0 = blockIdx.x * 128, n0 = blockIdx.y * 128;
    const int koff = blockIdx.z * 512;          // real-k offset (split-K=2)
    float* C = Cbase + (size_t)blockIdx.z * M * NCOLS;
    const int wm = (warp >> 2) * 32, wn = (warp & 3) * 32;
    const int NK = 16;                          // 512 / 32
    const int arow = tid >> 2, aq = tid & 3;    // x loader: row, 8-float quarter

    float acc[2][4][4];
#pragma unroll
    for (int i = 0; i < 2; i++)
#pragma unroll
        for (int j = 0; j < 4; j++)
#pragma unroll
            for (int k = 0; k < 4; k++) acc[i][j][k] = 0.f;

    float4 fv[2];
    auto ldgA = [&](int it) {
        if (it >= NK) return;
        const float* src = x + (size_t)(m0 + arow) * D_DIM + koff + it * 32 + aq * 8;
        fv[0] = *(const float4*)(src);
        fv[1] = *(const float4*)(src + 4);
    };
    auto stsA = [&](int it) {          // convert fv -> ah AND al tiles
        if (it >= NK) return;
        uint32_t dst = sb + (it % 3) * STAGE1 + arow * ROWB1 + aq * 16;
        uint32_t ph[4], pl[4];
        const float* f = (const float*)fv;
#pragma unroll
        for (int j = 0; j < 4; j++) {
            float v0 = f[2 * j], v1 = f[2 * j + 1];
            __nv_bfloat16 h0, l0, h1, l1;
            bsplit(v0, h0, l0); bsplit(v1, h1, l1);
            __nv_bfloat162 th = __halves2bfloat162(h0, h1);
            __nv_bfloat162 tl = __halves2bfloat162(l0, l1);
            ph[j] = *(uint32_t*)&th;
            pl[j] = *(uint32_t*)&tl;
        }
        asm volatile("st.shared.v4.b32 [%0], {%1,%2,%3,%4};"
                     :: "r"(dst), "r"(ph[0]), "r"(ph[1]), "r"(ph[2]), "r"(ph[3]));
        asm volatile("st.shared.v4.b32 [%0], {%1,%2,%3,%4};"
                     :: "r"(dst + AL_OFF), "r"(pl[0]), "r"(pl[1]), "r"(pl[2]), "r"(pl[3]));
    };
    auto cpB = [&](int it) {           // bh + bl tiles
        if (it < NK) {
            int k0 = koff + it * 32;
            uint32_t base = sb + (it % 3) * STAGE1;
            int row = tid >> 2, s = tid & 3;
            const __nv_bfloat16* src = B1 + (size_t)(n0 + row) * 2048 + k0 + s * 8;
            cp16(base + BH_OFF + row * ROWB1 + s * 16, src);
            cp16(base + BL_OFF + row * ROWB1 + s * 16, src + 1024);
        }
        CP_COMMIT();
    };

    ldgA(0); stsA(0);
    ldgA(1);
    cpB(0); cpB(1);

    for (int it = 0; it < NK; it++) {
        CP_WAIT(1);
        __syncthreads();
        stsA(it + 1);
        ldgA(it + 2);
        cpB(it + 2);

        const uint32_t sBase = sb + (it % 3) * STAGE1;
#pragma unroll
        for (int ks = 0; ks < 2; ks++) {
            const uint32_t kb = (ks * 16 + (lane >> 4) * 8) * 2;
            uint32_t ah[2][4], al[2][4], bh[2][4], bl[2][4];
#pragma unroll
            for (int mf = 0; mf < 2; mf++) {
                uint32_t ra = sBase + (wm + mf * 16 + (lane & 15)) * ROWB1 + kb;
                ldsm4(ah[mf], ra);
                ldsm4(al[mf], ra + AL_OFF);
            }
#pragma unroll
            for (int nf2 = 0; nf2 < 2; nf2++) {
                uint32_t rb = sBase + (wn + nf2 * 16 + (lane & 15)) * ROWB1 + kb;
                ldsm4(bh[nf2], rb + BH_OFF);
                ldsm4(bl[nf2], rb + BL_OFF);
            }
#pragma unroll
            for (int mf = 0; mf < 2; mf++)
#pragma unroll
                for (int nf = 0; nf < 4; nf++) {
                    uint32_t h0 = bh[nf >> 1][(nf & 1) ? 1 : 0];
                    uint32_t h1 = bh[nf >> 1][(nf & 1) ? 3 : 2];
                    uint32_t l0 = bl[nf >> 1][(nf & 1) ? 1 : 0];
                    uint32_t l1 = bl[nf >> 1][(nf & 1) ? 3 : 2];
                    mma16816(acc[mf][nf], ah[mf], h0, h1);
                    mma16816(acc[mf][nf], al[mf], h0, h1);
                    mma16816(acc[mf][nf], ah[mf], l0, l1);
                }
        }
    }

#pragma unroll
    for (int mf = 0; mf < 2; mf++)
#pragma unroll
        for (int nf = 0; nf < 4; nf++) {
            int row = m0 + wm + mf * 16 + (lane >> 2);
            int col = n0 + wn + nf * 8 + 2 * (lane & 3);
            *(float2*)&C[(size_t)row * NCOLS + col] =
                make_float2(acc[mf][nf][0], acc[mf][nf][1]);
            *(float2*)&C[(size_t)(row + 8) * NCOLS + col] =
                make_float2(acc[mf][nf][2], acc[mf][nf][3]);
        }
}

// ================= GEMM2: presplit bf16, BK=64, 3 stages =================
#define ROWB2  144                    // 64 bf16 + 16 B pad
#define T2     (128 * ROWB2)          // 18432
#define STAGE2 (2 * T2)               // 36864 (A + B)
#define SMEM2  (3 * STAGE2)           // 110592

__global__ __launch_bounds__(512)
void gemm_bf16(const __nv_bfloat16* __restrict__ A, const __nv_bfloat16* __restrict__ B,
               float* __restrict__ C, int M, int N, int KB, int KA) {
    extern __shared__ char smem[];
    const uint32_t sb = smem_u32(smem);
    const int tid = threadIdx.x, warp = tid >> 5, lane = tid & 31;
    const int m0 = blockIdx.x * 128, n0 = blockIdx.y * 128;
    const int wm = (warp >> 2) * 32, wn = (warp & 3) * 32;
    const int NK = KB / 64;

    float acc[2][4][4];
#pragma unroll
    for (int i = 0; i < 2; i++)
#pragma unroll
        for (int j = 0; j < 4; j++)
#pragma unroll
            for (int k = 0; k < 4; k++) acc[i][j][k] = 0.f;

    auto cpAB = [&](int it) {
        if (it < NK) {
            int k0 = it * 64;
            int ka = (k0 < KA) ? k0 : k0 - KA;
            uint32_t aB = sb + (it % 3) * STAGE2;
            uint32_t bB = aB + T2;
#pragma unroll
            for (int i = 0; i < 2; i++) {
                int idx = tid + i * 512;
                int row = idx >> 3, s = idx & 7;
                cp16(aB + row * ROWB2 + s * 16, A + (size_t)(m0 + row) * KA + ka + s * 8);
                cp16(bB + row * ROWB2 + s * 16, B + (size_t)(n0 + row) * KB + k0 + s * 8);
            }
        }
        CP_COMMIT();
    };

    cpAB(0); cpAB(1);

    for (int it = 0; it < NK; it++) {
        CP_WAIT(1);
        __syncthreads();
        cpAB(it + 2);

        const uint32_t aB = sb + (it % 3) * STAGE2;
        const uint32_t bB = aB + T2;
#pragma unroll
        for (int ks = 0; ks < 4; ks++) {
            const uint32_t kb = (ks * 16 + (lane >> 4) * 8) * 2;
            uint32_t ar[2][4], br[2][4];
#pragma unroll
            for (int mf = 0; mf < 2; mf++)
                ldsm4(ar[mf], aB + (wm + mf * 16 + (lane & 15)) * ROWB2 + kb);
#pragma unroll
            for (int nf2 = 0; nf2 < 2; nf2++)
                ldsm4(br[nf2], bB + (wn + nf2 * 16 + (lane & 15)) * ROWB2 + kb);
#pragma unroll
            for (int mf = 0; mf < 2; mf++)
#pragma unroll
                for (int nf = 0; nf < 4; nf++) {
                    uint32_t b0 = br[nf >> 1][(nf & 1) ? 1 : 0];
                    uint32_t b1 = br[nf >> 1][(nf & 1) ? 3 : 2];
                    mma16816(acc[mf][nf], ar[mf], b0, b1);
                }
        }
    }

#pragma unroll
    for (int mf = 0; mf < 2; mf++)
#pragma unroll
        for (int nf = 0; nf < 4; nf++) {
            int row = m0 + wm + mf * 16 + (lane >> 2);
            int col = n0 + wn + nf * 8 + 2 * (lane & 3);
            *(float2*)&C[(size_t)row * N + col] =
                make_float2(acc[mf][nf][0], acc[mf][nf][1]);
            *(float2*)&C[(size_t)(row + 8) * N + col] =
                make_float2(acc[mf][nf][2], acc[mf][nf][3]);
        }
}

// ---------------- pack weights ----------------
__global__ void pack_weights(const float* __restrict__ dw, const float* __restrict__ db,
                             const float* __restrict__ leaf, const float* __restrict__ gw,
                             const float* __restrict__ gb, const float* __restrict__ ntl) {
    int tid = blockIdx.x * blockDim.x + threadIdx.x;
    int stride = gridDim.x * blockDim.x;
    for (int i = tid; i < 240 * D_DIM; i += stride) {
        int n = i >> 10, d = i & 1023;
        __nv_bfloat16 h, l; bsplit(dw[i], h, l);
        size_t r = (size_t)n * 2048;
        g_B1[r + d] = h; g_B1[r + 1024 + d] = l;
    }
    for (int i = tid; i < 16 * D_DIM; i += stride) {
        int t = i >> 10, d = i & 1023;
        __nv_bfloat16 h, l; bsplit(gw[d * 16 + t], h, l);
        size_t r = (size_t)(240 + t) * 2048;
        g_B1[r + d] = h; g_B1[r + 1024 + d] = l;
    }
    for (int i = tid; i < O_DIM * 256; i += stride) {
        int o = i >> 8, k = i & 255;
        __nv_bfloat16 h, l; bsplit(leaf[(size_t)k * O_DIM + o], h, l);
        size_t r = (size_t)o * 768;
        g_B2[r + k] = h; g_B2[r + 256 + k] = h; g_B2[r + 512 + k] = l;
    }
    if (tid < 240) {
        g_bias[tid] = db[tid];
        float z = ntl[tid] + 0.5413f;
        float sp = (z > 20.f) ? z : log1pf(expf(z));
        g_invtemp[tid] = 1.0f / sp;
    } else if (tid < 256) {
        g_bias[tid] = gb[tid - 240];
    }
}

// ------- combine split-K partials + bias, gate softmax, path products -> A2 -------
__global__ __launch_bounds__(256)
void build_w_kernel(int M) {
    __shared__ float sl[8][256];
    int w = threadIdx.x >> 5;
    int lane = threadIdx.x & 31;
    int tok = blockIdx.x * 8 + w;
    if (tok >= M) return;

    const float4* s0 = (const float4*)&g_logits[(size_t)tok * NCOLS];
    const float4* s1 = (const float4*)&g_logits[(size_t)(M + tok) * NCOLS];
    const float4* bb = (const float4*)g_bias;
    float4* dst4 = (float4*)sl[w];
#pragma unroll
    for (int i = 0; i < 2; i++) {
        int j = lane + 32 * i;
        float4 a = s0[j], b = s1[j], c = bb[j];
        dst4[j] = make_float4(a.x + b.x + c.x, a.y + b.y + c.y,
                              a.z + b.z + c.z, a.w + b.w + c.w);
    }
    __syncwarp();
    const float* lrow = sl[w];

    float gl = (lane < 16) ? lrow[240 + lane] : -INFINITY;
    float mx = gl;
#pragma unroll
    for (int o = 16; o > 0; o >>= 1) mx = fmaxf(mx, __shfl_xor_sync(0xffffffffu, mx, o));
    float e = (lane < 16) ? expf(gl - mx) : 0.f;
    float s = e;
#pragma unroll
    for (int o = 16; o > 0; o >>= 1) s += __shfl_xor_sync(0xffffffffu, s, o);
    float gate = e / s;

    if (lane < 16) {
        int t = lane;
        float dec[15];
#pragma unroll
        for (int n = 0; n < 15; n++) {
            float z = lrow[t * 15 + n] * g_invtemp[t * 15 + n];
            dec[n] = 1.f / (1.f + expf(-z));
        }
        __nv_bfloat162 hi[8], lo[8];
#pragma unroll
        for (int leaf = 0; leaf < 16; leaf += 2) {
            __nv_bfloat16 h[2], l[2];
#pragma unroll
            for (int q = 0; q < 2; q++) {
                int lf = leaf + q;
                float p = gate;
                int node = 0;
#pragma unroll
                for (int d = 0; d < 4; d++) {
                    int bit = (lf >> (3 - d)) & 1;
                    float dv = dec[node];
                    p *= bit ? (1.f - dv) : dv;
                    node = 2 * node + 1 + bit;
                }
                bsplit(p, h[q], l[q]);
            }
            hi[leaf >> 1] = __halves2bfloat162(h[0], h[1]);
            lo[leaf >> 1] = __halves2bfloat162(l[0], l[1]);
        }
        size_t base = (size_t)tok * 512 + t * 16;
        *(uint4*)&g_A2[base]       = ((uint4*)hi)[0];
        *(uint4*)&g_A2[base + 8]   = ((uint4*)hi)[1];
        *(uint4*)&g_A2[base + 256] = ((uint4*)lo)[0];
        *(uint4*)&g_A2[base + 264] = ((uint4*)lo)[1];
    }
}

// ---------------- in-place LayerNorm over O=512 ----------------
__global__ __launch_bounds__(256)
void layernorm_kernel(float* __restrict__ out, const float* __restrict__ gamma,
                      const float* __restrict__ beta, int M) {
    int tok = (blockIdx.x * blockDim.x + threadIdx.x) >> 5;
    int lane = threadIdx.x & 31;
    if (tok >= M) return;
    float* row = out + (size_t)tok * O_DIM;

    float v[16], s = 0.f, sq = 0.f;
#pragma unroll
    for (int i = 0; i < 16; i++) {
        v[i] = row[lane + 32 * i];
        s += v[i]; sq += v[i] * v[i];
    }
#pragma unroll
    for (int o = 16; o > 0; o >>= 1) {
        s  += __shfl_xor_sync(0xffffffffu, s, o);
        sq += __shfl_xor_sync(0xffffffffu, sq, o);
    }
    float mu = s * (1.f / O_DIM);
    float var = sq * (1.f / O_DIM) - mu * mu;
    float inv = rsqrtf(var + 1e-5f);
#pragma unroll
    for (int i = 0; i < 16; i++) {
        int c = lane + 32 * i;
        row[c] = (v[i] - mu) * inv * gamma[c] + beta[c];
    }
}

// ---------------- launch ----------------
extern "C" void kernel_launch(void* const* d_in, const int* in_sizes, int n_in,
                              void* d_out, int out_size) {
    const float* x     = (const float*)d_in[0];
    const float* dw    = (const float*)d_in[1];
    const float* db    = (const float*)d_in[2];
    const float* leaf  = (const float*)d_in[3];
    const float* gw    = (const float*)d_in[4];
    const float* gb    = (const float*)d_in[5];
    const float* ntl   = (const float*)d_in[6];
    const float* gamma = (const float*)d_in[7];
    const float* beta  = (const float*)d_in[8];
    float* out = (float*)d_out;

    int M = in_sizes[0] / D_DIM;   // 8192

    void *pB1, *pA2, *pB2, *pLogits;
    cudaGetSymbolAddress(&pB1, g_B1);
    cudaGetSymbolAddress(&pA2, g_A2);
    cudaGetSymbolAddress(&pB2, g_B2);
    cudaGetSymbolAddress(&pLogits, g_logits);

    static bool attr_set = false;
    if (!attr_set) {
        cudaFuncSetAttribute(gemm1_fused, cudaFuncAttributeMaxDynamicSharedMemorySize,
                             SMEM1);
        cudaFuncSetAttribute(gemm_bf16, cudaFuncAttributeMaxDynamicSharedMemorySize,
                             SMEM2);
        attr_set = true;
    }

    // 0) weight packing (small)
    pack_weights<<<1024, 256>>>(dw, db, leaf, gw, gb, ntl);

    // 1) GEMM1 (fused split of x, hi/lo shared tiles), split-K=2 over real K=1024
    gemm1_fused<<<dim3(M / 128, 2, 2), 512, SMEM1>>>(
        x, (const __nv_bfloat16*)pB1, (float*)pLogits, M);

    // 2) combine partials + bias, gate softmax, path products -> A2 (split)
    build_w_kernel<<<M / 8, 256>>>(M);

    // 3) GEMM2: out[M,512] = split(Wl) @ split(leaf)^T, K'=768
    gemm_bf16<<<dim3(M / 128, 4), 512, SMEM2>>>(
        (const __nv_bfloat16*)pA2, (const __nv_bfloat16*)pB2, out, M, O_DIM, 768, 512);

    // 4) LayerNorm
    layernorm_kernel<<<M / 8, 256>>>(out, gamma, beta, M);
}

// round 7
// speedup vs baseline: 2.1895x; 1.0149x over previous
#include <cuda_runtime.h>
#include <cuda_bf16.h>
#include <math.h>
#include <stdint.h>

// ---------------- problem constants ----------------
#define D_DIM 1024
#define NCOLS 256      // 240 decision + 16 gate logits
#define O_DIM 512
#define M_MAX 8192

// GEMM1: B1 [256, 2048] = [hi|lo] (x split fused in-kernel)
// GEMM2: A2 [M,512]=[hi|lo], B2 [512,768]=[hi|hi|lo]
__device__ __align__(16) __nv_bfloat16 g_B1[NCOLS * 2048];
__device__ __align__(16) __nv_bfloat16 g_A2[M_MAX * 512];
__device__ __align__(16) __nv_bfloat16 g_B2[O_DIM * 768];
__device__ __align__(16) float g_logits[2 * M_MAX * NCOLS];   // split-K partials
__device__ __align__(16) float g_bias[NCOLS];
__device__ float g_invtemp[240];

// ---------------- helpers ----------------
__device__ __forceinline__ uint32_t smem_u32(const void* p) {
    uint32_t a;
    asm("{ .reg .u64 t; cvta.to.shared.u64 t, %1; cvt.u32.u64 %0, t; }"
        : "=r"(a) : "l"(p));
    return a;
}
__device__ __forceinline__ void cp16(uint32_t s, const void* g) {
    asm volatile("cp.async.cg.shared.global [%0], [%1], 16;" :: "r"(s), "l"(g));
}
#define CP_COMMIT() asm volatile("cp.async.commit_group;" ::: "memory")
#define CP_WAIT(n)  asm volatile("cp.async.wait_group %0;" :: "n"(n) : "memory")

__device__ __forceinline__ void ldsm4(uint32_t r[4], uint32_t addr) {
    asm volatile("ldmatrix.sync.aligned.m8n8.x4.shared.b16 {%0,%1,%2,%3}, [%4];"
                 : "=r"(r[0]), "=r"(r[1]), "=r"(r[2]), "=r"(r[3]) : "r"(addr));
}
__device__ __forceinline__ void mma16816(float c[4], const uint32_t a[4],
                                         uint32_t b0, uint32_t b1) {
    asm volatile(
        "mma.sync.aligned.m16n8k16.row.col.f32.bf16.bf16.f32 "
        "{%0,%1,%2,%3}, {%4,%5,%6,%7}, {%8,%9}, {%0,%1,%2,%3};"
        : "+f"(c[0]), "+f"(c[1]), "+f"(c[2]), "+f"(c[3])
        : "r"(a[0]), "r"(a[1]), "r"(a[2]), "r"(a[3]), "r"(b0), "r"(b1));
}
__device__ __forceinline__ void bsplit(float v, __nv_bfloat16& h, __nv_bfloat16& l) {
    h = __float2bfloat16(v);
    l = __float2bfloat16(v - __bfloat162float(h));
}

// ================= GEMM1: fused-split x, hi/lo shared-tile 3-term =================
// CTA 64x128, 256 thr (8 warps, 32x32 warptiles), BK=32 real-k, 2-stage.
#define ROWB1  80                     // 32 bf16 + 8 B pad
#define AH_OFF 0                      // 64 x 80  = 5120
#define AL_OFF 5120
#define BH_OFF 10240                  // 128 x 80 = 10240
#define BL_OFF 20480
#define STAGE1 30720
#define SMEM1  (2 * STAGE1)           // 61440

__global__ __launch_bounds__(256, 3)
void gemm1_fused(const float* __restrict__ x, const __nv_bfloat16* __restrict__ B1,
                 float* __restrict__ Cbase, int M) {
    extern __shared__ char smem[];
    const uint32_t sb = smem_u32(smem);
    const int tid = threadIdx.x, warp = tid >> 5, lane = tid & 31;
    const int m0 = blockIdx.x * 64, n0 = blockIdx.y * 128;
    const int koff = blockIdx.z * 512;          // split-K=2
    float* C = Cbase + (size_t)blockIdx.z * M * NCOLS;
    const int wm = (warp >> 2) * 32, wn = (warp & 3) * 32;
    const int NK = 16;                          // 512 / 32
    const int arow = tid >> 2, aq = tid & 3;    // x loader: row 0..63, 8-float quarter

    float acc[2][4][4];
#pragma unroll
    for (int i = 0; i < 2; i++)
#pragma unroll
        for (int j = 0; j < 4; j++)
#pragma unroll
            for (int k = 0; k < 4; k++) acc[i][j][k] = 0.f;

    float4 fv[2];
    auto ldgA = [&](int it) {
        if (it >= NK) return;
        const float* src = x + (size_t)(m0 + arow) * D_DIM + koff + it * 32 + aq * 8;
        fv[0] = *(const float4*)(src);
        fv[1] = *(const float4*)(src + 4);
    };
    auto stsA = [&](int it) {          // convert fv -> ah AND al tiles
        if (it >= NK) return;
        uint32_t dst = sb + (it & 1) * STAGE1 + arow * ROWB1 + aq * 16;
        uint32_t ph[4], pl[4];
        const float* f = (const float*)fv;
#pragma unroll
        for (int j = 0; j < 4; j++) {
            float v0 = f[2 * j], v1 = f[2 * j + 1];
            __nv_bfloat16 h0, l0, h1, l1;
            bsplit(v0, h0, l0); bsplit(v1, h1, l1);
            __nv_bfloat162 th = __halves2bfloat162(h0, h1);
            __nv_bfloat162 tl = __halves2bfloat162(l0, l1);
            ph[j] = *(uint32_t*)&th;
            pl[j] = *(uint32_t*)&tl;
        }
        asm volatile("st.shared.v4.b32 [%0], {%1,%2,%3,%4};"
                     :: "r"(dst + AH_OFF), "r"(ph[0]), "r"(ph[1]), "r"(ph[2]), "r"(ph[3]));
        asm volatile("st.shared.v4.b32 [%0], {%1,%2,%3,%4};"
                     :: "r"(dst + AL_OFF), "r"(pl[0]), "r"(pl[1]), "r"(pl[2]), "r"(pl[3]));
    };
    auto cpB = [&](int it) {           // bh + bl tiles (128 rows x 32 bf16)
        if (it < NK) {
            int k0 = koff + it * 32;
            uint32_t base = sb + (it & 1) * STAGE1;
#pragma unroll
            for (int i = 0; i < 2; i++) {
                int idx = tid + i * 256;
                int row = idx >> 2, s = idx & 3;
                const __nv_bfloat16* src = B1 + (size_t)(n0 + row) * 2048 + k0 + s * 8;
                cp16(base + BH_OFF + row * ROWB1 + s * 16, src);
                cp16(base + BL_OFF + row * ROWB1 + s * 16, src + 1024);
            }
        }
        CP_COMMIT();
    };

    ldgA(0); stsA(0);
    ldgA(1);
    cpB(0); cpB(1);

    for (int it = 0; it < NK; it++) {
        CP_WAIT(1);
        __syncthreads();

        const uint32_t sBase = sb + (it & 1) * STAGE1;
#pragma unroll
        for (int ks = 0; ks < 2; ks++) {
            const uint32_t kb = (ks * 16 + (lane >> 4) * 8) * 2;
            uint32_t ah[2][4], al[2][4], bh[2][4], bl[2][4];
#pragma unroll
            for (int mf = 0; mf < 2; mf++) {
                uint32_t ra = sBase + (wm + mf * 16 + (lane & 15)) * ROWB1 + kb;
                ldsm4(ah[mf], ra + AH_OFF);
                ldsm4(al[mf], ra + AL_OFF);
            }
#pragma unroll
            for (int nf2 = 0; nf2 < 2; nf2++) {
                uint32_t rb = sBase + (wn + nf2 * 16 + (lane & 15)) * ROWB1 + kb;
                ldsm4(bh[nf2], rb + BH_OFF);
                ldsm4(bl[nf2], rb + BL_OFF);
            }
#pragma unroll
            for (int mf = 0; mf < 2; mf++)
#pragma unroll
                for (int nf = 0; nf < 4; nf++) {
                    uint32_t h0 = bh[nf >> 1][(nf & 1) ? 1 : 0];
                    uint32_t h1 = bh[nf >> 1][(nf & 1) ? 3 : 2];
                    uint32_t l0 = bl[nf >> 1][(nf & 1) ? 1 : 0];
                    uint32_t l1 = bl[nf >> 1][(nf & 1) ? 3 : 2];
                    mma16816(acc[mf][nf], ah[mf], h0, h1);
                    mma16816(acc[mf][nf], al[mf], h0, h1);
                    mma16816(acc[mf][nf], ah[mf], l0, l1);
                }
        }

        stsA(it + 1);        // A tile it+1 into the other buffer (safe: synced)
        ldgA(it + 2);        // refill fv
        __syncthreads();     // all reads of buffer (it&1) done before overwrite
        cpB(it + 2);         // async B tile it+2 into buffer (it&1)
    }

#pragma unroll
    for (int mf = 0; mf < 2; mf++)
#pragma unroll
        for (int nf = 0; nf < 4; nf++) {
            int row = m0 + wm + mf * 16 + (lane >> 2);
            int col = n0 + wn + nf * 8 + 2 * (lane & 3);
            *(float2*)&C[(size_t)row * NCOLS + col] =
                make_float2(acc[mf][nf][0], acc[mf][nf][1]);
            *(float2*)&C[(size_t)(row + 8) * NCOLS + col] =
                make_float2(acc[mf][nf][2], acc[mf][nf][3]);
        }
}

// ================= GEMM2: presplit bf16, CTA 64x128, BK=64, 2-stage =================
#define ROWB2  144                    // 64 bf16 + 16 B pad
#define T2A    (64 * ROWB2)           // 9216
#define STAGE2 (T2A + 128 * ROWB2)    // 27648
#define SMEM2  (2 * STAGE2)           // 55296

__global__ __launch_bounds__(256, 4)
void gemm_bf16(const __nv_bfloat16* __restrict__ A, const __nv_bfloat16* __restrict__ B,
               float* __restrict__ C, int M, int N, int KB, int KA) {
    extern __shared__ char smem[];
    const uint32_t sb = smem_u32(smem);
    const int tid = threadIdx.x, warp = tid >> 5, lane = tid & 31;
    const int m0 = blockIdx.x * 64, n0 = blockIdx.y * 128;
    const int wm = (warp >> 2) * 32, wn = (warp & 3) * 32;
    const int NK = KB / 64;

    float acc[2][4][4];
#pragma unroll
    for (int i = 0; i < 2; i++)
#pragma unroll
        for (int j = 0; j < 4; j++)
#pragma unroll
            for (int k = 0; k < 4; k++) acc[i][j][k] = 0.f;

    auto cpAB = [&](int it) {
        if (it < NK) {
            int k0 = it * 64;
            int ka = (k0 < KA) ? k0 : k0 - KA;
            uint32_t aB = sb + (it & 1) * STAGE2;
            uint32_t bB = aB + T2A;
#pragma unroll
            for (int i = 0; i < 2; i++) {       // A: 64 rows x 8 segs
                int idx = tid + i * 256;
                int row = idx >> 3, s = idx & 7;
                cp16(aB + row * ROWB2 + s * 16, A + (size_t)(m0 + row) * KA + ka + s * 8);
            }
#pragma unroll
            for (int i = 0; i < 4; i++) {       // B: 128 rows x 8 segs
                int idx = tid + i * 256;
                int row = idx >> 3, s = idx & 7;
                cp16(bB + row * ROWB2 + s * 16, B + (size_t)(n0 + row) * KB + k0 + s * 8);
            }
        }
        CP_COMMIT();
    };

    cpAB(0); cpAB(1);

    for (int it = 0; it < NK; it++) {
        CP_WAIT(1);
        __syncthreads();

        const uint32_t aB = sb + (it & 1) * STAGE2;
        const uint32_t bB = aB + T2A;
#pragma unroll
        for (int ks = 0; ks < 4; ks++) {
            const uint32_t kb = (ks * 16 + (lane >> 4) * 8) * 2;
            uint32_t ar[2][4], br[2][4];
#pragma unroll
            for (int mf = 0; mf < 2; mf++)
                ldsm4(ar[mf], aB + (wm + mf * 16 + (lane & 15)) * ROWB2 + kb);
#pragma unroll
            for (int nf2 = 0; nf2 < 2; nf2++)
                ldsm4(br[nf2], bB + (wn + nf2 * 16 + (lane & 15)) * ROWB2 + kb);
#pragma unroll
            for (int mf = 0; mf < 2; mf++)
#pragma unroll
                for (int nf = 0; nf < 4; nf++) {
                    uint32_t b0 = br[nf >> 1][(nf & 1) ? 1 : 0];
                    uint32_t b1 = br[nf >> 1][(nf & 1) ? 3 : 2];
                    mma16816(acc[mf][nf], ar[mf], b0, b1);
                }
        }

        __syncthreads();
        cpAB(it + 2);
    }

#pragma unroll
    for (int mf = 0; mf < 2; mf++)
#pragma unroll
        for (int nf = 0; nf < 4; nf++) {
            int row = m0 + wm + mf * 16 + (lane >> 2);
            int col = n0 + wn + nf * 8 + 2 * (lane & 3);
            *(float2*)&C[(size_t)row * N + col] =
                make_float2(acc[mf][nf][0], acc[mf][nf][1]);
            *(float2*)&C[(size_t)(row + 8) * N + col] =
                make_float2(acc[mf][nf][2], acc[mf][nf][3]);
        }
}

// ---------------- pack weights ----------------
__global__ void pack_weights(const float* __restrict__ dw, const float* __restrict__ db,
                             const float* __restrict__ leaf, const float* __restrict__ gw,
                             const float* __restrict__ gb, const float* __restrict__ ntl) {
    int tid = blockIdx.x * blockDim.x + threadIdx.x;
    int stride = gridDim.x * blockDim.x;
    for (int i = tid; i < 240 * D_DIM; i += stride) {
        int n = i >> 10, d = i & 1023;
        __nv_bfloat16 h, l; bsplit(dw[i], h, l);
        size_t r = (size_t)n * 2048;
        g_B1[r + d] = h; g_B1[r + 1024 + d] = l;
    }
    for (int i = tid; i < 16 * D_DIM; i += stride) {
        int t = i >> 10, d = i & 1023;
        __nv_bfloat16 h, l; bsplit(gw[d * 16 + t], h, l);
        size_t r = (size_t)(240 + t) * 2048;
        g_B1[r + d] = h; g_B1[r + 1024 + d] = l;
    }
    for (int i = tid; i < O_DIM * 256; i += stride) {
        int o = i >> 8, k = i & 255;
        __nv_bfloat16 h, l; bsplit(leaf[(size_t)k * O_DIM + o], h, l);
        size_t r = (size_t)o * 768;
        g_B2[r + k] = h; g_B2[r + 256 + k] = h; g_B2[r + 512 + k] = l;
    }
    if (tid < 240) {
        g_bias[tid] = db[tid];
        float z = ntl[tid] + 0.5413f;
        float sp = (z > 20.f) ? z : log1pf(expf(z));
        g_invtemp[tid] = 1.0f / sp;
    } else if (tid < 256) {
        g_bias[tid] = gb[tid - 240];
    }
}

// ------- combine split-K partials + bias, gate softmax, path products -> A2 -------
__global__ __launch_bounds__(256)
void build_w_kernel(int M) {
    __shared__ float sl[8][256];
    int w = threadIdx.x >> 5;
    int lane = threadIdx.x & 31;
    int tok = blockIdx.x * 8 + w;
    if (tok >= M) return;

    const float4* s0 = (const float4*)&g_logits[(size_t)tok * NCOLS];
    const float4* s1 = (const float4*)&g_logits[(size_t)(M + tok) * NCOLS];
    const float4* bb = (const float4*)g_bias;
    float4* dst4 = (float4*)sl[w];
#pragma unroll
    for (int i = 0; i < 2; i++) {
        int j = lane + 32 * i;
        float4 a = s0[j], b = s1[j], c = bb[j];
        dst4[j] = make_float4(a.x + b.x + c.x, a.y + b.y + c.y,
                              a.z + b.z + c.z, a.w + b.w + c.w);
    }
    __syncwarp();
    const float* lrow = sl[w];

    float gl = (lane < 16) ? lrow[240 + lane] : -INFINITY;
    float mx = gl;
#pragma unroll
    for (int o = 16; o > 0; o >>= 1) mx = fmaxf(mx, __shfl_xor_sync(0xffffffffu, mx, o));
    float e = (lane < 16) ? expf(gl - mx) : 0.f;
    float s = e;
#pragma unroll
    for (int o = 16; o > 0; o >>= 1) s += __shfl_xor_sync(0xffffffffu, s, o);
    float gate = e / s;

    if (lane < 16) {
        int t = lane;
        float dec[15];
#pragma unroll
        for (int n = 0; n < 15; n++) {
            float z = lrow[t * 15 + n] * g_invtemp[t * 15 + n];
            dec[n] = 1.f / (1.f + expf(-z));
        }
        __nv_bfloat162 hi[8], lo[8];
#pragma unroll
        for (int leaf = 0; leaf < 16; leaf += 2) {
            __nv_bfloat16 h[2], l[2];
#pragma unroll
            for (int q = 0; q < 2; q++) {
                int lf = leaf + q;
                float p = gate;
                int node = 0;
#pragma unroll
                for (int d = 0; d < 4; d++) {
                    int bit = (lf >> (3 - d)) & 1;
                    float dv = dec[node];
                    p *= bit ? (1.f - dv) : dv;
                    node = 2 * node + 1 + bit;
                }
                bsplit(p, h[q], l[q]);
            }
            hi[leaf >> 1] = __halves2bfloat162(h[0], h[1]);
            lo[leaf >> 1] = __halves2bfloat162(l[0], l[1]);
        }
        size_t base = (size_t)tok * 512 + t * 16;
        *(uint4*)&g_A2[base]       = ((uint4*)hi)[0];
        *(uint4*)&g_A2[base + 8]   = ((uint4*)hi)[1];
        *(uint4*)&g_A2[base + 256] = ((uint4*)lo)[0];
        *(uint4*)&g_A2[base + 264] = ((uint4*)lo)[1];
    }
}

// ---------------- in-place LayerNorm over O=512 ----------------
__global__ __launch_bounds__(256)
void layernorm_kernel(float* __restrict__ out, const float* __restrict__ gamma,
                      const float* __restrict__ beta, int M) {
    int tok = (blockIdx.x * blockDim.x + threadIdx.x) >> 5;
    int lane = threadIdx.x & 31;
    if (tok >= M) return;
    float* row = out + (size_t)tok * O_DIM;

    float v[16], s = 0.f, sq = 0.f;
#pragma unroll
    for (int i = 0; i < 16; i++) {
        v[i] = row[lane + 32 * i];
        s += v[i]; sq += v[i] * v[i];
    }
#pragma unroll
    for (int o = 16; o > 0; o >>= 1) {
        s  += __shfl_xor_sync(0xffffffffu, s, o);
        sq += __shfl_xor_sync(0xffffffffu, sq, o);
    }
    float mu = s * (1.f / O_DIM);
    float var = sq * (1.f / O_DIM) - mu * mu;
    float inv = rsqrtf(var + 1e-5f);
#pragma unroll
    for (int i = 0; i < 16; i++) {
        int c = lane + 32 * i;
        row[c] = (v[i] - mu) * inv * gamma[c] + beta[c];
    }
}

// ---------------- launch ----------------
extern "C" void kernel_launch(void* const* d_in, const int* in_sizes, int n_in,
                              void* d_out, int out_size) {
    const float* x     = (const float*)d_in[0];
    const float* dw    = (const float*)d_in[1];
    const float* db    = (const float*)d_in[2];
    const float* leaf  = (const float*)d_in[3];
    const float* gw    = (const float*)d_in[4];
    const float* gb    = (const float*)d_in[5];
    const float* ntl   = (const float*)d_in[6];
    const float* gamma = (const float*)d_in[7];
    const float* beta  = (const float*)d_in[8];
    float* out = (float*)d_out;

    int M = in_sizes[0] / D_DIM;   // 8192

    void *pB1, *pA2, *pB2, *pLogits;
    cudaGetSymbolAddress(&pB1, g_B1);
    cudaGetSymbolAddress(&pA2, g_A2);
    cudaGetSymbolAddress(&pB2, g_B2);
    cudaGetSymbolAddress(&pLogits, g_logits);

    static bool attr_set = false;
    if (!attr_set) {
        cudaFuncSetAttribute(gemm1_fused, cudaFuncAttributeMaxDynamicSharedMemorySize,
                             SMEM1);
        cudaFuncSetAttribute(gemm_bf16, cudaFuncAttributeMaxDynamicSharedMemorySize,
                             SMEM2);
        attr_set = true;
    }

    // 0) weight packing (small)
    pack_weights<<<1024, 256>>>(dw, db, leaf, gw, gb, ntl);

    // 1) GEMM1 (fused split of x, hi/lo shared tiles), split-K=2 over real K=1024
    gemm1_fused<<<dim3(M / 64, 2, 2), 256, SMEM1>>>(
        x, (const __nv_bfloat16*)pB1, (float*)pLogits, M);

    // 2) combine partials + bias, gate softmax, path products -> A2 (split)
    build_w_kernel<<<M / 8, 256>>>(M);

    // 3) GEMM2: out[M,512] = split(Wl) @ split(leaf)^T, K'=768
    gemm_bf16<<<dim3(M / 64, 4), 256, SMEM2>>>(
        (const __nv_bfloat16*)pA2, (const __nv_bfloat16*)pB2, out, M, O_DIM, 768, 512);

    // 4) LayerNorm
    layernorm_kernel<<<M / 8, 256>>>(out, gamma, beta, M);
}

// round 8
// speedup vs baseline: 2.2086x; 1.0087x over previous
#include <cuda_runtime.h>
#include <cuda_bf16.h>
#include <math.h>
#include <stdint.h>

// ---------------- problem constants ----------------
#define D_DIM 1024
#define NCOLS 256      // 240 decision + 16 gate logits
#define O_DIM 512
#define M_MAX 8192

// GEMM1: B1 [256, 2048] = [hi|lo] (x split fused in-kernel)
// GEMM2: B2 [512, 768] = [hi|hi|lo]; A built in-smem by the mega kernel
__device__ __align__(16) __nv_bfloat16 g_B1[NCOLS * 2048];
__device__ __align__(16) __nv_bfloat16 g_B2[O_DIM * 768];
__device__ __align__(16) float g_logits[2 * M_MAX * NCOLS];   // split-K partials
__device__ __align__(16) float g_bias[NCOLS];
__device__ float g_invtemp[240];

// ---------------- helpers ----------------
__device__ __forceinline__ uint32_t smem_u32(const void* p) {
    uint32_t a;
    asm("{ .reg .u64 t; cvta.to.shared.u64 t, %1; cvt.u32.u64 %0, t; }"
        : "=r"(a) : "l"(p));
    return a;
}
__device__ __forceinline__ void cp16(uint32_t s, const void* g) {
    asm volatile("cp.async.cg.shared.global [%0], [%1], 16;" :: "r"(s), "l"(g));
}
#define CP_COMMIT() asm volatile("cp.async.commit_group;" ::: "memory")
#define CP_WAIT(n)  asm volatile("cp.async.wait_group %0;" :: "n"(n) : "memory")

__device__ __forceinline__ void ldsm4(uint32_t r[4], uint32_t addr) {
    asm volatile("ldmatrix.sync.aligned.m8n8.x4.shared.b16 {%0,%1,%2,%3}, [%4];"
                 : "=r"(r[0]), "=r"(r[1]), "=r"(r[2]), "=r"(r[3]) : "r"(addr));
}
__device__ __forceinline__ void mma16816(float c[4], const uint32_t a[4],
                                         uint32_t b0, uint32_t b1) {
    asm volatile(
        "mma.sync.aligned.m16n8k16.row.col.f32.bf16.bf16.f32 "
        "{%0,%1,%2,%3}, {%4,%5,%6,%7}, {%8,%9}, {%0,%1,%2,%3};"
        : "+f"(c[0]), "+f"(c[1]), "+f"(c[2]), "+f"(c[3])
        : "r"(a[0]), "r"(a[1]), "r"(a[2]), "r"(a[3]), "r"(b0), "r"(b1));
}
__device__ __forceinline__ void bsplit(float v, __nv_bfloat16& h, __nv_bfloat16& l) {
    h = __float2bfloat16(v);
    l = __float2bfloat16(v - __bfloat162float(h));
}

// ================= GEMM1: fused-split x, hi/lo shared-tile 3-term =================
// (unchanged from R7 — runs at ~93% of the mma.sync roofline)
#define ROWB1  80
#define AH_OFF 0
#define AL_OFF 5120
#define BH_OFF 10240
#define BL_OFF 20480
#define STAGE1 30720
#define SMEM1  (2 * STAGE1)           // 61440

__global__ __launch_bounds__(256, 3)
void gemm1_fused(const float* __restrict__ x, const __nv_bfloat16* __restrict__ B1,
                 float* __restrict__ Cbase, int M) {
    extern __shared__ char smem[];
    const uint32_t sb = smem_u32(smem);
    const int tid = threadIdx.x, warp = tid >> 5, lane = tid & 31;
    const int m0 = blockIdx.x * 64, n0 = blockIdx.y * 128;
    const int koff = blockIdx.z * 512;          // split-K=2
    float* C = Cbase + (size_t)blockIdx.z * M * NCOLS;
    const int wm = (warp >> 2) * 32, wn = (warp & 3) * 32;
    const int NK = 16;
    const int arow = tid >> 2, aq = tid & 3;

    float acc[2][4][4];
#pragma unroll
    for (int i = 0; i < 2; i++)
#pragma unroll
        for (int j = 0; j < 4; j++)
#pragma unroll
            for (int k = 0; k < 4; k++) acc[i][j][k] = 0.f;

    float4 fv[2];
    auto ldgA = [&](int it) {
        if (it >= NK) return;
        const float* src = x + (size_t)(m0 + arow) * D_DIM + koff + it * 32 + aq * 8;
        fv[0] = *(const float4*)(src);
        fv[1] = *(const float4*)(src + 4);
    };
    auto stsA = [&](int it) {
        if (it >= NK) return;
        uint32_t dst = sb + (it & 1) * STAGE1 + arow * ROWB1 + aq * 16;
        uint32_t ph[4], pl[4];
        const float* f = (const float*)fv;
#pragma unroll
        for (int j = 0; j < 4; j++) {
            float v0 = f[2 * j], v1 = f[2 * j + 1];
            __nv_bfloat16 h0, l0, h1, l1;
            bsplit(v0, h0, l0); bsplit(v1, h1, l1);
            __nv_bfloat162 th = __halves2bfloat162(h0, h1);
            __nv_bfloat162 tl = __halves2bfloat162(l0, l1);
            ph[j] = *(uint32_t*)&th;
            pl[j] = *(uint32_t*)&tl;
        }
        asm volatile("st.shared.v4.b32 [%0], {%1,%2,%3,%4};"
                     :: "r"(dst + AH_OFF), "r"(ph[0]), "r"(ph[1]), "r"(ph[2]), "r"(ph[3]));
        asm volatile("st.shared.v4.b32 [%0], {%1,%2,%3,%4};"
                     :: "r"(dst + AL_OFF), "r"(pl[0]), "r"(pl[1]), "r"(pl[2]), "r"(pl[3]));
    };
    auto cpB = [&](int it) {
        if (it < NK) {
            int k0 = koff + it * 32;
            uint32_t base = sb + (it & 1) * STAGE1;
#pragma unroll
            for (int i = 0; i < 2; i++) {
                int idx = tid + i * 256;
                int row = idx >> 2, s = idx & 3;
                const __nv_bfloat16* src = B1 + (size_t)(n0 + row) * 2048 + k0 + s * 8;
                cp16(base + BH_OFF + row * ROWB1 + s * 16, src);
                cp16(base + BL_OFF + row * ROWB1 + s * 16, src + 1024);
            }
        }
        CP_COMMIT();
    };

    ldgA(0); stsA(0);
    ldgA(1);
    cpB(0); cpB(1);

    for (int it = 0; it < NK; it++) {
        CP_WAIT(1);
        __syncthreads();

        const uint32_t sBase = sb + (it & 1) * STAGE1;
#pragma unroll
        for (int ks = 0; ks < 2; ks++) {
            const uint32_t kb = (ks * 16 + (lane >> 4) * 8) * 2;
            uint32_t ah[2][4], al[2][4], bh[2][4], bl[2][4];
#pragma unroll
            for (int mf = 0; mf < 2; mf++) {
                uint32_t ra = sBase + (wm + mf * 16 + (lane & 15)) * ROWB1 + kb;
                ldsm4(ah[mf], ra + AH_OFF);
                ldsm4(al[mf], ra + AL_OFF);
            }
#pragma unroll
            for (int nf2 = 0; nf2 < 2; nf2++) {
                uint32_t rb = sBase + (wn + nf2 * 16 + (lane & 15)) * ROWB1 + kb;
                ldsm4(bh[nf2], rb + BH_OFF);
                ldsm4(bl[nf2], rb + BL_OFF);
            }
#pragma unroll
            for (int mf = 0; mf < 2; mf++)
#pragma unroll
                for (int nf = 0; nf < 4; nf++) {
                    uint32_t h0 = bh[nf >> 1][(nf & 1) ? 1 : 0];
                    uint32_t h1 = bh[nf >> 1][(nf & 1) ? 3 : 2];
                    uint32_t l0 = bl[nf >> 1][(nf & 1) ? 1 : 0];
                    uint32_t l1 = bl[nf >> 1][(nf & 1) ? 3 : 2];
                    mma16816(acc[mf][nf], ah[mf], h0, h1);
                    mma16816(acc[mf][nf], al[mf], h0, h1);
                    mma16816(acc[mf][nf], ah[mf], l0, l1);
                }
        }

        stsA(it + 1);
        ldgA(it + 2);
        __syncthreads();
        cpB(it + 2);
    }

#pragma unroll
    for (int mf = 0; mf < 2; mf++)
#pragma unroll
        for (int nf = 0; nf < 4; nf++) {
            int row = m0 + wm + mf * 16 + (lane >> 2);
            int col = n0 + wn + nf * 8 + 2 * (lane & 3);
            *(float2*)&C[(size_t)row * NCOLS + col] =
                make_float2(acc[mf][nf][0], acc[mf][nf][1]);
            *(float2*)&C[(size_t)(row + 8) * NCOLS + col] =
                make_float2(acc[mf][nf][2], acc[mf][nf][3]);
        }
}

// ================= MEGA: build_w + GEMM2 + LayerNorm fused =================
// CTA: 64 tokens x FULL N=512. A (split Wl, [hi|lo] 512 cols) lives in smem.
// 512 threads = 16 warps, warptile 32x64 (2 m-warps x 8 n-warps).
#define G2_STAT 0                        // [64][8][2] f32 row stats = 4096 B
#define G2_A    4096                     // A2: 64 rows x 1040 B (520 bf16)
#define G2_AROW 1040
#define G2_B0   (4096 + 64 * 1040)       // 70656
#define G2_BROW 144                      // 64 bf16 + 16 B pad
#define G2_BSTG (512 * G2_BROW)          // 73728
#define G2_SMEM (G2_B0 + 2 * G2_BSTG)    // 218112

__global__ __launch_bounds__(512)
void gemm2_mega(const float* __restrict__ logits, const __nv_bfloat16* __restrict__ B2,
                const float* __restrict__ gamma, const float* __restrict__ beta,
                float* __restrict__ out, int M) {
    extern __shared__ char smem[];
    const uint32_t sb = smem_u32(smem);
    const int tid = threadIdx.x, warp = tid >> 5, lane = tid & 31;
    const int m0 = blockIdx.x * 64;
    const int wm = (warp >> 3) * 32, wn = (warp & 7) * 64;

    // ---- prologue 1: combine split-K partials + bias -> smem f32 [64][264] ----
    float* slog = (float*)(smem + G2_B0);     // temp in B stage-0 area
    {
        const float4* s0 = (const float4*)(logits + (size_t)m0 * NCOLS);
        const float4* s1 = (const float4*)(logits + (size_t)(M + m0) * NCOLS);
        const float4* bb = (const float4*)g_bias;
#pragma unroll
        for (int i = 0; i < 8; i++) {
            int j = tid + i * 512;            // 0..4095 over 64 tok x 64 float4
            int row = j >> 6, q = j & 63;
            float4 a = s0[(size_t)row * 64 + q], b = s1[(size_t)row * 64 + q], c = bb[q];
            ((float4*)(slog + row * 264))[q] =
                make_float4(a.x + b.x + c.x, a.y + b.y + c.y,
                            a.z + b.z + c.z, a.w + b.w + c.w);
        }
    }
    __syncthreads();

    // ---- prologue 2: gate softmax + sigmoids + paths -> A smem (split bf16) ----
#pragma unroll
    for (int i = 0; i < 4; i++) {
        int tok = warp * 4 + i;
        const float* lrow = slog + tok * 264;
        float gl = (lane < 16) ? lrow[240 + lane] : -INFINITY;
        float mx = gl;
#pragma unroll
        for (int o = 16; o > 0; o >>= 1) mx = fmaxf(mx, __shfl_xor_sync(0xffffffffu, mx, o));
        float e = (lane < 16) ? expf(gl - mx) : 0.f;
        float s = e;
#pragma unroll
        for (int o = 16; o > 0; o >>= 1) s += __shfl_xor_sync(0xffffffffu, s, o);
        float gate = e / s;

        if (lane < 16) {
            int t = lane;
            float dec[15];
#pragma unroll
            for (int n = 0; n < 15; n++) {
                float z = lrow[t * 15 + n] * g_invtemp[t * 15 + n];
                dec[n] = 1.f / (1.f + expf(-z));
            }
            __nv_bfloat162 hi[8], lo[8];
#pragma unroll
            for (int leaf = 0; leaf < 16; leaf += 2) {
                __nv_bfloat16 h[2], l[2];
#pragma unroll
                for (int q2 = 0; q2 < 2; q2++) {
                    int lf = leaf + q2;
                    float p = gate;
                    int node = 0;
#pragma unroll
                    for (int d = 0; d < 4; d++) {
                        int bit = (lf >> (3 - d)) & 1;
                        float dv = dec[node];
                        p *= bit ? (1.f - dv) : dv;
                        node = 2 * node + 1 + bit;
                    }
                    bsplit(p, h[q2], l[q2]);
                }
                hi[leaf >> 1] = __halves2bfloat162(h[0], h[1]);
                lo[leaf >> 1] = __halves2bfloat162(l[0], l[1]);
            }
            char* arow = smem + G2_A + tok * G2_AROW + t * 32;
            *(uint4*)(arow)             = ((uint4*)hi)[0];
            *(uint4*)(arow + 16)        = ((uint4*)hi)[1];
            *(uint4*)(arow + 512)       = ((uint4*)lo)[0];   // lo at col 256
            *(uint4*)(arow + 512 + 16)  = ((uint4*)lo)[1];
        }
    }
    __syncthreads();   // slog reads done; A ready; B pipeline may overwrite stage 0

    // ---- main loop: stream B2 tiles (K'=768, BK=64), A resident in smem ----
    float acc[2][8][4];
#pragma unroll
    for (int i = 0; i < 2; i++)
#pragma unroll
        for (int j = 0; j < 8; j++)
#pragma unroll
            for (int k = 0; k < 4; k++) acc[i][j][k] = 0.f;

    auto cpB = [&](int it) {
        if (it < 12) {
            int k0 = it * 64;
            uint32_t bB = sb + G2_B0 + (it & 1) * G2_BSTG;
#pragma unroll
            for (int i = 0; i < 8; i++) {
                int idx = tid + i * 512;
                int row = idx >> 3, s = idx & 7;
                cp16(bB + row * G2_BROW + s * 16, B2 + (size_t)row * 768 + k0 + s * 8);
            }
        }
        CP_COMMIT();
    };

    cpB(0); cpB(1);

    for (int it = 0; it < 12; it++) {
        CP_WAIT(1);
        __syncthreads();

        const uint32_t bB = sb + G2_B0 + (it & 1) * G2_BSTG;
#pragma unroll
        for (int ks = 0; ks < 4; ks++) {
            int k = it * 64 + ks * 16;
            int ka = (k < 512) ? k : k - 512;    // 3rd B segment reuses A-hi
            uint32_t ah[2][4], br[4][4];
            uint32_t ra = sb + G2_A + (lane & 15) * G2_AROW + (ka + (lane >> 4) * 8) * 2;
            ldsm4(ah[0], ra + wm * G2_AROW);
            ldsm4(ah[1], ra + (wm + 16) * G2_AROW);
            uint32_t kb = (ks * 16 + (lane >> 4) * 8) * 2;
#pragma unroll
            for (int nf2 = 0; nf2 < 4; nf2++)
                ldsm4(br[nf2], bB + (wn + nf2 * 16 + (lane & 15)) * G2_BROW + kb);
#pragma unroll
            for (int mf = 0; mf < 2; mf++)
#pragma unroll
                for (int nf = 0; nf < 8; nf++) {
                    uint32_t b0 = br[nf >> 1][(nf & 1) ? 1 : 0];
                    uint32_t b1 = br[nf >> 1][(nf & 1) ? 3 : 2];
                    mma16816(acc[mf][nf], ah[mf], b0, b1);
                }
        }

        __syncthreads();
        cpB(it + 2);
    }

    // ---- epilogue: fused LayerNorm over N=512 ----
    float* stats = (float*)smem;   // [64][8][2]
#pragma unroll
    for (int i = 0; i < 4; i++) {
        int mf = i >> 1, half = i & 1;
        float s = 0.f, q = 0.f;
#pragma unroll
        for (int nf = 0; nf < 8; nf++) {
            float v0 = acc[mf][nf][half * 2 + 0], v1 = acc[mf][nf][half * 2 + 1];
            s += v0 + v1; q += v0 * v0 + v1 * v1;
        }
        s += __shfl_xor_sync(0xffffffffu, s, 1); q += __shfl_xor_sync(0xffffffffu, q, 1);
        s += __shfl_xor_sync(0xffffffffu, s, 2); q += __shfl_xor_sync(0xffffffffu, q, 2);
        if ((lane & 3) == 0) {
            int row = wm + mf * 16 + half * 8 + (lane >> 2);
            stats[(row * 8 + (warp & 7)) * 2 + 0] = s;
            stats[(row * 8 + (warp & 7)) * 2 + 1] = q;
        }
    }
    __syncthreads();

#pragma unroll
    for (int i = 0; i < 4; i++) {
        int mf = i >> 1, half = i & 1;
        int row = wm + mf * 16 + half * 8 + (lane >> 2);
        float s = 0.f, q = 0.f;
#pragma unroll
        for (int w8 = 0; w8 < 8; w8++) {
            s += stats[(row * 8 + w8) * 2 + 0];
            q += stats[(row * 8 + w8) * 2 + 1];
        }
        float mu = s * (1.f / 512.f);
        float var = q * (1.f / 512.f) - mu * mu;
        float istd = rsqrtf(var + 1e-5f);
        float* orow = out + (size_t)(m0 + row) * O_DIM;
#pragma unroll
        for (int nf = 0; nf < 8; nf++) {
            int col = wn + nf * 8 + 2 * (lane & 3);
            float2 g2 = __ldg((const float2*)&gamma[col]);
            float2 b2 = __ldg((const float2*)&beta[col]);
            float v0 = (acc[mf][nf][half * 2 + 0] - mu) * istd * g2.x + b2.x;
            float v1 = (acc[mf][nf][half * 2 + 1] - mu) * istd * g2.y + b2.y;
            *(float2*)&orow[col] = make_float2(v0, v1);
        }
    }
}

// ---------------- pack weights ----------------
__global__ void pack_weights(const float* __restrict__ dw, const float* __restrict__ db,
                             const float* __restrict__ leaf, const float* __restrict__ gw,
                             const float* __restrict__ gb, const float* __restrict__ ntl) {
    int tid = blockIdx.x * blockDim.x + threadIdx.x;
    int stride = gridDim.x * blockDim.x;
    for (int i = tid; i < 240 * D_DIM; i += stride) {
        int n = i >> 10, d = i & 1023;
        __nv_bfloat16 h, l; bsplit(dw[i], h, l);
        size_t r = (size_t)n * 2048;
        g_B1[r + d] = h; g_B1[r + 1024 + d] = l;
    }
    for (int i = tid; i < 16 * D_DIM; i += stride) {
        int t = i >> 10, d = i & 1023;
        __nv_bfloat16 h, l; bsplit(gw[d * 16 + t], h, l);
        size_t r = (size_t)(240 + t) * 2048;
        g_B1[r + d] = h; g_B1[r + 1024 + d] = l;
    }
    for (int i = tid; i < O_DIM * 256; i += stride) {
        int o = i >> 8, k = i & 255;
        __nv_bfloat16 h, l; bsplit(leaf[(size_t)k * O_DIM + o], h, l);
        size_t r = (size_t)o * 768;
        g_B2[r + k] = h; g_B2[r + 256 + k] = h; g_B2[r + 512 + k] = l;
    }
    if (tid < 240) {
        g_bias[tid] = db[tid];
        float z = ntl[tid] + 0.5413f;
        float sp = (z > 20.f) ? z : log1pf(expf(z));
        g_invtemp[tid] = 1.0f / sp;
    } else if (tid < 256) {
        g_bias[tid] = gb[tid - 240];
    }
}

// ---------------- launch ----------------
extern "C" void kernel_launch(void* const* d_in, const int* in_sizes, int n_in,
                              void* d_out, int out_size) {
    const float* x     = (const float*)d_in[0];
    const float* dw    = (const float*)d_in[1];
    const float* db    = (const float*)d_in[2];
    const float* leaf  = (const float*)d_in[3];
    const float* gw    = (const float*)d_in[4];
    const float* gb    = (const float*)d_in[5];
    const float* ntl   = (const float*)d_in[6];
    const float* gamma = (const float*)d_in[7];
    const float* beta  = (const float*)d_in[8];
    float* out = (float*)d_out;

    int M = in_sizes[0] / D_DIM;   // 8192

    void *pB1, *pB2, *pLogits;
    cudaGetSymbolAddress(&pB1, g_B1);
    cudaGetSymbolAddress(&pB2, g_B2);
    cudaGetSymbolAddress(&pLogits, g_logits);

    static bool attr_set = false;
    if (!attr_set) {
        cudaFuncSetAttribute(gemm1_fused, cudaFuncAttributeMaxDynamicSharedMemorySize,
                             SMEM1);
        cudaFuncSetAttribute(gemm2_mega, cudaFuncAttributeMaxDynamicSharedMemorySize,
                             G2_SMEM);
        attr_set = true;
    }

    // 0) weight packing (small)
    pack_weights<<<1024, 256>>>(dw, db, leaf, gw, gb, ntl);

    // 1) GEMM1 (fused split of x), split-K=2 over real K=1024 -> partials
    gemm1_fused<<<dim3(M / 64, 2, 2), 256, SMEM1>>>(
        x, (const __nv_bfloat16*)pB1, (float*)pLogits, M);

    // 2) MEGA: combine + gate/tree + GEMM2 + LayerNorm -> out
    gemm2_mega<<<M / 64, 512, G2_SMEM>>>(
        (const float*)pLogits, (const __nv_bfloat16*)pB2, gamma, beta, out, M);
}